// round 8
// baseline (speedup 1.0000x reference)
#include <cuda_runtime.h>
#include <math.h>

#define BATCH 4
#define LQ 2048
#define LK 2048
#define DMODEL 512
#define NH 2
#define DK 64
#define DV 64
#define QKV_N 128

#define BQ 64
#define BK 64

#define Q_STR 68
#define K_STR 68
#define OFF_Q 0
#define OFF_K (OFF_Q + DK * Q_STR)        // 4352
#define OFF_V (OFF_K + DK * K_STR)        // 8704
#define OFF_S (OFF_V + BK * DV)           // 12800
#define OFF_RL (OFF_S + BK * BQ)          // 16896
#define OFF_LSE (OFF_RL + BQ)
#define OFF_MSK (OFF_LSE + BQ)
#define SMEM_FLOATS (OFF_MSK + BK)        // 17088
#define SMEM_BYTES (SMEM_FLOATS * 4)      // 68352

typedef unsigned long long ull;

__device__ __forceinline__ ull pk2(float x, float y)
{ ull r; asm("mov.b64 %0,{%1,%2};" : "=l"(r) : "f"(x), "f"(y)); return r; }
__device__ __forceinline__ ull bc2(float x) { return pk2(x, x); }
__device__ __forceinline__ void fma2(ull& d, ull a, ull b)
{ asm("fma.rn.f32x2 %0,%1,%2,%0;" : "+l"(d) : "l"(a), "l"(b)); }
__device__ __forceinline__ float2 up2(ull v)
{ float2 r; asm("mov.b64 {%0,%1},%2;" : "=f"(r.x), "=f"(r.y) : "l"(v)); return r; }

// S tile [kc][64q], q-group swizzled; offsets stay 16B-aligned (g<<2 floats)
__device__ __forceinline__ int s_off(int kc, int g)
{ return OFF_S + kc * 64 + (((g + (kc >> 2)) & 15) << 2); }

// 10*tanh(x) = 10 - 20/(exp(2x)+1); exact at +/-inf
__device__ __forceinline__ float tanh10(float x)
{
    float e = __expf(2.f * x);
    float r;
    asm("rcp.approx.f32 %0,%1;" : "=f"(r) : "f"(e + 1.f));
    return fmaf(-20.f, r, 10.f);
}

__device__ float g_q[BATCH * LQ * QKV_N];
__device__ float g_k[BATCH * LK * QKV_N];
__device__ float g_v[BATCH * LK * QKV_N];
__device__ float g_otmp[BATCH * LQ * QKV_N];
__device__ float g_vsum[BATCH * QKV_N];
__device__ int g_mask_mode;  // 0=u8, 1=i32, 2=f32

__global__ void detect_mask_kernel(const unsigned int* __restrict__ w)
{
    __shared__ int s_f32, s_all01;
    if (threadIdx.x == 0) { s_f32 = 0; s_all01 = 1; }
    __syncthreads();
    int f = 0, bad = 0;
    for (int i = threadIdx.x; i < 2048; i += blockDim.x) {
        unsigned v = w[i];
        if (v == 0x3F800000u) f = 1;
        if (v > 1u) bad = 1;
    }
    if (f) atomicOr(&s_f32, 1);
    if (bad) atomicExch(&s_all01, 0);
    __syncthreads();
    if (threadIdx.x == 0) g_mask_mode = s_f32 ? 2 : (s_all01 ? 1 : 0);
}

// ---- fused QKV projection
__global__ __launch_bounds__(256) void gemm_qkv_kernel(
    const float* __restrict__ X0, const float* __restrict__ X1, const float* __restrict__ X2,
    const float* __restrict__ W0, const float* __restrict__ W1, const float* __restrict__ W2,
    const float* __restrict__ B0, const float* __restrict__ B1, const float* __restrict__ B2,
    float* __restrict__ Y0, float* __restrict__ Y1, float* __restrict__ Y2)
{
    __shared__ float xs[32 * 68];
    __shared__ float ws[32 * 132];
    int sel = blockIdx.y;
    const float* X = sel == 0 ? X0 : (sel == 1 ? X1 : X2);
    const float* W = sel == 0 ? W0 : (sel == 1 ? W1 : W2);
    const float* bias = sel == 0 ? B0 : (sel == 1 ? B1 : B2);
    float* Y = sel == 0 ? Y0 : (sel == 1 ? Y1 : Y2);

    int tid = threadIdx.x;
    int tx = tid & 15, ty = tid >> 4;
    int bm = blockIdx.x * 64;
    int row0 = ty * 4, col0 = tx * 8;

    ull acc2[4][4];
#pragma unroll
    for (int i = 0; i < 4; i++)
#pragma unroll
        for (int j = 0; j < 4; j++) acc2[i][j] = 0ull;

    for (int k0 = 0; k0 < DMODEL; k0 += 32) {
#pragma unroll
        for (int i = 0; i < 2; i++) {
            int linear = tid + i * 256;
            int m = linear >> 3;
            int g = (linear & 7) * 4;
            float4 v = *(const float4*)&X[(size_t)(bm + m) * DMODEL + k0 + g];
            xs[(g + 0) * 68 + m] = v.x;
            xs[(g + 1) * 68 + m] = v.y;
            xs[(g + 2) * 68 + m] = v.z;
            xs[(g + 3) * 68 + m] = v.w;
        }
#pragma unroll
        for (int i = 0; i < 4; i++) {
            int linear = tid + i * 256;
            int k = linear >> 5;
            int g = (linear & 31) * 4;
            *(float4*)&ws[k * 132 + g] = *(const float4*)&W[(size_t)(k0 + k) * QKV_N + g];
        }
        __syncthreads();
#pragma unroll
        for (int k = 0; k < 32; k++) {
            float4 xa = *(const float4*)&xs[k * 68 + row0];
            float4 wa = *(const float4*)&ws[k * 132 + col0];
            float4 wb = *(const float4*)&ws[k * 132 + col0 + 4];
            ull wp[4] = {pk2(wa.x, wa.y), pk2(wa.z, wa.w),
                         pk2(wb.x, wb.y), pk2(wb.z, wb.w)};
            ull xb[4] = {bc2(xa.x), bc2(xa.y), bc2(xa.z), bc2(xa.w)};
#pragma unroll
            for (int i = 0; i < 4; i++)
#pragma unroll
                for (int j = 0; j < 4; j++)
                    fma2(acc2[i][j], xb[i], wp[j]);
        }
        __syncthreads();
    }
    float bb[8];
#pragma unroll
    for (int j = 0; j < 8; j++) bb[j] = bias[col0 + j];
#pragma unroll
    for (int i = 0; i < 4; i++) {
        float2 a0 = up2(acc2[i][0]), a1 = up2(acc2[i][1]);
        float2 a2 = up2(acc2[i][2]), a3 = up2(acc2[i][3]);
        float* yp = &Y[(size_t)(bm + row0 + i) * QKV_N + col0];
        *(float4*)yp = make_float4(a0.x + bb[0], a0.y + bb[1], a1.x + bb[2], a1.y + bb[3]);
        *(float4*)(yp + 4) = make_float4(a2.x + bb[4], a2.y + bb[5], a3.x + bb[6], a3.y + bb[7]);
    }
}

// ---- out-proj GEMM
__global__ __launch_bounds__(256) void gemm_bias_kernel(
    const float* __restrict__ X, const float* __restrict__ W,
    const float* __restrict__ bias, float* __restrict__ Y,
    int M, int K, int N)
{
    __shared__ float xs[32 * 68];
    __shared__ float ws[32 * 132];
    int tid = threadIdx.x;
    int tx = tid & 15, ty = tid >> 4;
    int bm = blockIdx.x * 64, bn = blockIdx.y * 128;
    int row0 = ty * 4, col0 = tx * 8;

    ull acc2[4][4];
#pragma unroll
    for (int i = 0; i < 4; i++)
#pragma unroll
        for (int j = 0; j < 4; j++) acc2[i][j] = 0ull;

    for (int k0 = 0; k0 < K; k0 += 32) {
#pragma unroll
        for (int i = 0; i < 2; i++) {
            int linear = tid + i * 256;
            int m = linear >> 3;
            int g = (linear & 7) * 4;
            float4 v = *(const float4*)&X[(size_t)(bm + m) * K + k0 + g];
            xs[(g + 0) * 68 + m] = v.x;
            xs[(g + 1) * 68 + m] = v.y;
            xs[(g + 2) * 68 + m] = v.z;
            xs[(g + 3) * 68 + m] = v.w;
        }
#pragma unroll
        for (int i = 0; i < 4; i++) {
            int linear = tid + i * 256;
            int k = linear >> 5;
            int g = (linear & 31) * 4;
            *(float4*)&ws[k * 132 + g] = *(const float4*)&W[(size_t)(k0 + k) * N + bn + g];
        }
        __syncthreads();
#pragma unroll
        for (int k = 0; k < 32; k++) {
            float4 xa = *(const float4*)&xs[k * 68 + row0];
            float4 wa = *(const float4*)&ws[k * 132 + col0];
            float4 wb = *(const float4*)&ws[k * 132 + col0 + 4];
            ull wp[4] = {pk2(wa.x, wa.y), pk2(wa.z, wa.w),
                         pk2(wb.x, wb.y), pk2(wb.z, wb.w)};
            ull xb[4] = {bc2(xa.x), bc2(xa.y), bc2(xa.z), bc2(xa.w)};
#pragma unroll
            for (int i = 0; i < 4; i++)
#pragma unroll
                for (int j = 0; j < 4; j++)
                    fma2(acc2[i][j], xb[i], wp[j]);
        }
        __syncthreads();
    }
    float bb[8];
#pragma unroll
    for (int j = 0; j < 8; j++) bb[j] = bias[bn + col0 + j];
#pragma unroll
    for (int i = 0; i < 4; i++) {
        float2 a0 = up2(acc2[i][0]), a1 = up2(acc2[i][1]);
        float2 a2 = up2(acc2[i][2]), a3 = up2(acc2[i][3]);
        float* yp = &Y[(size_t)(bm + row0 + i) * N + bn + col0];
        *(float4*)yp = make_float4(a0.x + bb[0], a0.y + bb[1], a1.x + bb[2], a1.y + bb[3]);
        *(float4*)(yp + 4) = make_float4(a2.x + bb[4], a2.y + bb[5], a3.x + bb[6], a3.y + bb[7]);
    }
}

__global__ void vsum_zero_kernel() { g_vsum[threadIdx.x] = 0.f; }

__global__ __launch_bounds__(256) void vsum_kernel()
{
    __shared__ float red[8][128];
    int b = blockIdx.x, part = blockIdx.y;
    int c4 = (threadIdx.x & 31) * 4;
    int r0 = threadIdx.x >> 5;
    const float* base = g_v + ((size_t)b * LK + part * 128) * QKV_N;
    float4 s = make_float4(0.f, 0.f, 0.f, 0.f);
#pragma unroll 4
    for (int r = r0; r < 128; r += 8) {
        float4 v = *(const float4*)&base[(size_t)r * QKV_N + c4];
        s.x += v.x; s.y += v.y; s.z += v.z; s.w += v.w;
    }
    *(float4*)&red[r0][c4] = s;
    __syncthreads();
    if (threadIdx.x < 128) {
        float t = 0.f;
#pragma unroll
        for (int i = 0; i < 8; i++) t += red[i][threadIdx.x];
        atomicAdd(&g_vsum[b * QKV_N + threadIdx.x], t);
    }
}

// one block = 64 queries for one (b,h); 256 threads, 2 CTAs/SM; frag 4x4
__global__ __launch_bounds__(256, 2) void mab_main_kernel(
    const void* __restrict__ maskp, float* __restrict__ attn)
{
    extern __shared__ float sm[];
    int tid = threadIdx.x;
    int tx = tid & 15, ty = tid >> 4;
    int m0 = ty * 4;
    int nk = tx * 4;
    int nv = tx * 4;
    int q0 = blockIdx.x * BQ;
    int h = blockIdx.y, b = blockIdx.z;
    int mode = g_mask_mode;

    // load Q [64q][64d] -> transposed [d][m], scaled by 1/8
    const float* qbase = g_q + ((size_t)b * LQ + q0) * QKV_N + h * DK;
#pragma unroll
    for (int i = 0; i < 4; i++) {
        int linear = tid + i * 256;
        int m = linear >> 4;
        int d = (linear & 15) * 4;
        float4 v = *(const float4*)&qbase[(size_t)m * QKV_N + d];
        sm[OFF_Q + (d + 0) * Q_STR + m] = v.x * 0.125f;
        sm[OFF_Q + (d + 1) * Q_STR + m] = v.y * 0.125f;
        sm[OFF_Q + (d + 2) * Q_STR + m] = v.z * 0.125f;
        sm[OFF_Q + (d + 3) * Q_STR + m] = v.w * 0.125f;
    }
    if (tid < BQ) sm[OFF_RL + tid] = 0.f;

    ull sv2[2][4];
#pragma unroll
    for (int i = 0; i < 2; i++)
#pragma unroll
        for (int j = 0; j < 4; j++) sv2[i][j] = 0ull;

    const float* kbase = g_k + (size_t)b * LK * QKV_N + h * DK;
    const float* vbase = g_v + (size_t)b * LK * QKV_N + h * DK;
    float* arow = attn + ((size_t)((b * NH + h) * LQ + q0)) * LK;

    __syncthreads();

    for (int c = 0; c < LK / BK; c++) {
        int k0 = c * BK;
        // K chunk transposed [d][kr]
#pragma unroll
        for (int i = 0; i < 4; i++) {
            int linear = tid + i * 256;
            int kr = linear >> 4;
            int d = (linear & 15) * 4;
            float4 v = *(const float4*)&kbase[(size_t)(k0 + kr) * QKV_N + d];
            sm[OFF_K + (d + 0) * K_STR + kr] = v.x;
            sm[OFF_K + (d + 1) * K_STR + kr] = v.y;
            sm[OFF_K + (d + 2) * K_STR + kr] = v.z;
            sm[OFF_K + (d + 3) * K_STR + kr] = v.w;
        }
        // V chunk natural [kr][dv]
#pragma unroll
        for (int i = 0; i < 4; i++) {
            int linear = tid + i * 256;
            int kr = linear >> 4;
            int d = (linear & 15) * 4;
            *(float4*)&sm[OFF_V + kr * DV + d] =
                *(const float4*)&vbase[(size_t)(k0 + kr) * QKV_N + d];
        }
        if (tid < BK) {
            size_t gi = (size_t)b * LK + k0 + tid;
            int mm;
            if (mode == 1)      mm = ((const int*)maskp)[gi] != 0;
            else if (mode == 0) mm = ((const unsigned char*)maskp)[gi] != 0;
            else                mm = ((const float*)maskp)[gi] != 0.f;
            sm[OFF_MSK + tid] = mm ? 1.f : 0.f;
        }
        __syncthreads();

        // phase 1: S = q @ k^T, 4 queries x 4 keys per thread
        ull acc2[2][4];
#pragma unroll
        for (int p = 0; p < 2; p++)
#pragma unroll
            for (int j = 0; j < 4; j++) acc2[p][j] = 0ull;

#pragma unroll 8
        for (int d = 0; d < DK; d++) {
            float4 qa = *(const float4*)&sm[OFF_Q + d * Q_STR + m0];
            float4 ka = *(const float4*)&sm[OFF_K + d * K_STR + nk];
            ull qp[2] = {pk2(qa.x, qa.y), pk2(qa.z, qa.w)};
            ull kb[4] = {bc2(ka.x), bc2(ka.y), bc2(ka.z), bc2(ka.w)};
#pragma unroll
            for (int p = 0; p < 2; p++)
#pragma unroll
                for (int j = 0; j < 4; j++)
                    fma2(acc2[p][j], qp[p], kb[j]);
        }

        float acc[4][4];
#pragma unroll
        for (int p = 0; p < 2; p++)
#pragma unroll
            for (int j = 0; j < 4; j++) {
                float2 v = up2(acc2[p][j]);
                acc[2 * p][j] = v.x;
                acc[2 * p + 1][j] = v.y;
            }

        float mk[4];
#pragma unroll
        for (int j = 0; j < 4; j++) mk[j] = sm[OFF_MSK + nk + j];

        // tanh-clip + mask + gmem write + fused exp row-sums
        float er[4];
#pragma unroll
        for (int i = 0; i < 4; i++) {
            float rs = 0.f;
#pragma unroll
            for (int j = 0; j < 4; j++) {
                float s = tanh10(acc[i][j]);
                if (mk[j] != 0.f) s = -10.f;
                acc[i][j] = s;
                rs += __expf(s);
            }
            er[i] = rs;
            *(float4*)&arow[(size_t)(m0 + i) * LK + k0 + nk] =
                make_float4(acc[i][0], acc[i][1], acc[i][2], acc[i][3]);
        }
#pragma unroll
        for (int d = 1; d < 16; d <<= 1) {
#pragma unroll
            for (int i = 0; i < 4; i++)
                er[i] += __shfl_xor_sync(0xffffffffu, er[i], d);
        }
        if (tx == 0) {
#pragma unroll
            for (int i = 0; i < 4; i++)
                sm[OFF_RL + m0 + i] += er[i];
        }
        // S tile to smem (swizzled; consumed by same half-warp)
#pragma unroll
        for (int j = 0; j < 4; j++) {
            int kc = nk + j;
            *(float4*)&sm[s_off(kc, ty)] =
                make_float4(acc[0][j], acc[1][j], acc[2][j], acc[3][j]);
        }
        __syncwarp();

        // phase 2: SV += S_chunk @ v_chunk (4 queries x 4 dv per thread)
#pragma unroll 8
        for (int kc = 0; kc < BK; kc++) {
            float4 sa = *(const float4*)&sm[s_off(kc, ty)];
            float4 vv = *(const float4*)&sm[OFF_V + kc * DV + nv];
            ull sp[2] = {pk2(sa.x, sa.y), pk2(sa.z, sa.w)};
            ull vb[4] = {bc2(vv.x), bc2(vv.y), bc2(vv.z), bc2(vv.w)};
#pragma unroll
            for (int p = 0; p < 2; p++)
#pragma unroll
                for (int j = 0; j < 4; j++)
                    fma2(sv2[p][j], sp[p], vb[j]);
        }
        __syncthreads();
    }

    if (tid < BQ) sm[OFF_LSE + tid] = logf(sm[OFF_RL + tid]);
    __syncthreads();

    {   // otmp = SV - lse * vsum
        float4 vs = *(const float4*)&g_vsum[(b * NH + h) * DV + nv];
#pragma unroll
        for (int p = 0; p < 2; p++) {
            float2 c0 = up2(sv2[p][0]), c1 = up2(sv2[p][1]);
            float2 c2 = up2(sv2[p][2]), c3 = up2(sv2[p][3]);
            float l0 = sm[OFF_LSE + m0 + 2 * p];
            float l1 = sm[OFF_LSE + m0 + 2 * p + 1];
            size_t r0 = ((size_t)b * LQ + q0 + m0 + 2 * p) * QKV_N + h * DK + nv;
            *(float4*)&g_otmp[r0] =
                make_float4(c0.x - l0 * vs.x, c1.x - l0 * vs.y,
                            c2.x - l0 * vs.z, c3.x - l0 * vs.w);
            *(float4*)&g_otmp[r0 + QKV_N] =
                make_float4(c0.y - l1 * vs.x, c1.y - l1 * vs.y,
                            c2.y - l1 * vs.z, c3.y - l1 * vs.w);
        }
    }

    float lr[4];
#pragma unroll
    for (int i = 0; i < 4; i++) lr[i] = sm[OFF_LSE + m0 + i];
    for (int c = 0; c < LK / BK; c++) {
#pragma unroll
        for (int i = 0; i < 4; i++) {
            float4* p = (float4*)&arow[(size_t)(m0 + i) * LK + c * BK + nk];
            float4 a = *p;
            a.x -= lr[i]; a.y -= lr[i]; a.z -= lr[i]; a.w -= lr[i];
            *p = a;
        }
    }
}

extern "C" void kernel_launch(void* const* d_in, const int* in_sizes, int n_in,
                              void* d_out, int out_size)
{
    const float* Q  = (const float*)d_in[0];
    const float* K  = (const float*)d_in[1];
    const float* V  = (const float*)d_in[2];
    const void*  Mk = d_in[3];
    const float* Wq = (const float*)d_in[4];
    const float* bq = (const float*)d_in[5];
    const float* Wk = (const float*)d_in[6];
    const float* bk = (const float*)d_in[7];
    const float* Wv = (const float*)d_in[8];
    const float* bv = (const float*)d_in[9];
    const float* Wo = (const float*)d_in[10];
    const float* bo = (const float*)d_in[11];

    float* out  = (float*)d_out;
    float* attn = out + (size_t)BATCH * LQ * DMODEL;

    float *gq, *gk, *gv, *gotmp;
    cudaGetSymbolAddress((void**)&gq, g_q);
    cudaGetSymbolAddress((void**)&gk, g_k);
    cudaGetSymbolAddress((void**)&gv, g_v);
    cudaGetSymbolAddress((void**)&gotmp, g_otmp);

    static int smem_set = 0;
    if (!smem_set) {
        cudaFuncSetAttribute(mab_main_kernel,
                             cudaFuncAttributeMaxDynamicSharedMemorySize, SMEM_BYTES);
        smem_set = 1;
    }

    detect_mask_kernel<<<1, 256>>>((const unsigned int*)Mk);

    const int M = BATCH * LQ;  // 8192
    gemm_qkv_kernel<<<dim3(M / 64, 3), 256>>>(Q, K, V, Wq, Wk, Wv,
                                              bq, bk, bv, gq, gk, gv);

    vsum_zero_kernel<<<1, BATCH * QKV_N>>>();
    vsum_kernel<<<dim3(BATCH, 16), 256>>>();

    mab_main_kernel<<<dim3(LQ / BQ, NH, BATCH), 256, SMEM_BYTES>>>(Mk, attn);

    gemm_bias_kernel<<<dim3(M / 64, DMODEL / 128), 256>>>(gotmp, Wo, bo, out,
                                                          M, QKV_N, DMODEL);
}

// round 9
// speedup vs baseline: 1.0829x; 1.0829x over previous
#include <cuda_runtime.h>
#include <math.h>

#define BATCH 4
#define LQ 2048
#define LK 2048
#define DMODEL 512
#define NH 2
#define DK 64
#define DV 64
#define QKV_N 128

#define BQ 128
#define BK 128

#define Q_STR 132
#define K_STR 132
#define OFF_Q 0
#define OFF_K (OFF_Q + DK * Q_STR)
#define OFF_V (OFF_K + DK * K_STR)
#define OFF_S (OFF_V + BK * DV)
#define OFF_RL (OFF_S + BK * BQ)
#define OFF_LSE (OFF_RL + BQ)
#define OFF_MSK (OFF_LSE + BQ)
#define SMEM_FLOATS (OFF_MSK + BK)
#define SMEM_BYTES (SMEM_FLOATS * 4)

typedef unsigned long long ull;

__device__ __forceinline__ ull pk2(float x, float y)
{ ull r; asm("mov.b64 %0,{%1,%2};" : "=l"(r) : "f"(x), "f"(y)); return r; }
__device__ __forceinline__ ull bc2(float x) { return pk2(x, x); }
__device__ __forceinline__ void fma2(ull& d, ull a, ull b)
{ asm("fma.rn.f32x2 %0,%1,%2,%0;" : "+l"(d) : "l"(a), "l"(b)); }
__device__ __forceinline__ float2 up2(ull v)
{ float2 r; asm("mov.b64 {%0,%1},%2;" : "=f"(r.x), "=f"(r.y) : "l"(v)); return r; }

__device__ __forceinline__ unsigned smem_u32(const void* p)
{
    unsigned a;
    asm("{ .reg .u64 t; cvta.to.shared.u64 t, %1; cvt.u32.u64 %0, t; }"
        : "=r"(a) : "l"(p));
    return a;
}
__device__ __forceinline__ void cp_async16(unsigned dst, const void* src)
{ asm volatile("cp.async.cg.shared.global [%0],[%1],16;" :: "r"(dst), "l"(src)); }
__device__ __forceinline__ void cp_async_commit()
{ asm volatile("cp.async.commit_group;"); }
__device__ __forceinline__ void cp_async_wait0()
{ asm volatile("cp.async.wait_group 0;"); }

__device__ __forceinline__ int s_off(int kc, int g)
{ return OFF_S + kc * BQ + (((g + kc + (kc >> 3)) & 31) << 2); }

// 10*tanh(x) = 10 - 20/(exp(2x)+1); exact at +/-inf
__device__ __forceinline__ float tanh10(float x)
{
    float e = __expf(2.f * x);
    float r;
    asm("rcp.approx.f32 %0,%1;" : "=f"(r) : "f"(e + 1.f));
    return fmaf(-20.f, r, 10.f);
}

__device__ float g_q[BATCH * LQ * QKV_N];
__device__ float g_k[BATCH * LK * QKV_N];
__device__ float g_v[BATCH * LK * QKV_N];
__device__ float g_otmp[BATCH * LQ * QKV_N];
__device__ float g_vsum[BATCH * QKV_N];
__device__ float g_lse[BATCH * NH * LQ];
__device__ int g_mask_mode;  // 0=u8, 1=i32, 2=f32

__global__ void detect_mask_kernel(const unsigned int* __restrict__ w)
{
    __shared__ int s_f32, s_all01;
    if (threadIdx.x == 0) { s_f32 = 0; s_all01 = 1; }
    __syncthreads();
    int f = 0, bad = 0;
    for (int i = threadIdx.x; i < 2048; i += blockDim.x) {
        unsigned v = w[i];
        if (v == 0x3F800000u) f = 1;
        if (v > 1u) bad = 1;
    }
    if (f) atomicOr(&s_f32, 1);
    if (bad) atomicExch(&s_all01, 0);
    __syncthreads();
    if (threadIdx.x == 0) g_mask_mode = s_f32 ? 2 : (s_all01 ? 1 : 0);
}

// ---- fused QKV projection
__global__ __launch_bounds__(256) void gemm_qkv_kernel(
    const float* __restrict__ X0, const float* __restrict__ X1, const float* __restrict__ X2,
    const float* __restrict__ W0, const float* __restrict__ W1, const float* __restrict__ W2,
    const float* __restrict__ B0, const float* __restrict__ B1, const float* __restrict__ B2,
    float* __restrict__ Y0, float* __restrict__ Y1, float* __restrict__ Y2)
{
    __shared__ float xs[32 * 68];
    __shared__ float ws[32 * 132];
    int sel = blockIdx.y;
    const float* X = sel == 0 ? X0 : (sel == 1 ? X1 : X2);
    const float* W = sel == 0 ? W0 : (sel == 1 ? W1 : W2);
    const float* bias = sel == 0 ? B0 : (sel == 1 ? B1 : B2);
    float* Y = sel == 0 ? Y0 : (sel == 1 ? Y1 : Y2);

    int tid = threadIdx.x;
    int tx = tid & 15, ty = tid >> 4;
    int bm = blockIdx.x * 64;
    int row0 = ty * 4, col0 = tx * 8;

    ull acc2[4][4];
#pragma unroll
    for (int i = 0; i < 4; i++)
#pragma unroll
        for (int j = 0; j < 4; j++) acc2[i][j] = 0ull;

    for (int k0 = 0; k0 < DMODEL; k0 += 32) {
#pragma unroll
        for (int i = 0; i < 2; i++) {
            int linear = tid + i * 256;
            int m = linear >> 3;
            int g = (linear & 7) * 4;
            float4 v = *(const float4*)&X[(size_t)(bm + m) * DMODEL + k0 + g];
            xs[(g + 0) * 68 + m] = v.x;
            xs[(g + 1) * 68 + m] = v.y;
            xs[(g + 2) * 68 + m] = v.z;
            xs[(g + 3) * 68 + m] = v.w;
        }
#pragma unroll
        for (int i = 0; i < 4; i++) {
            int linear = tid + i * 256;
            int k = linear >> 5;
            int g = (linear & 31) * 4;
            *(float4*)&ws[k * 132 + g] = *(const float4*)&W[(size_t)(k0 + k) * QKV_N + g];
        }
        __syncthreads();
#pragma unroll
        for (int k = 0; k < 32; k++) {
            float4 xa = *(const float4*)&xs[k * 68 + row0];
            float4 wa = *(const float4*)&ws[k * 132 + col0];
            float4 wb = *(const float4*)&ws[k * 132 + col0 + 4];
            ull wp[4] = {pk2(wa.x, wa.y), pk2(wa.z, wa.w),
                         pk2(wb.x, wb.y), pk2(wb.z, wb.w)};
            ull xb[4] = {bc2(xa.x), bc2(xa.y), bc2(xa.z), bc2(xa.w)};
#pragma unroll
            for (int i = 0; i < 4; i++)
#pragma unroll
                for (int j = 0; j < 4; j++)
                    fma2(acc2[i][j], xb[i], wp[j]);
        }
        __syncthreads();
    }
    float bb[8];
#pragma unroll
    for (int j = 0; j < 8; j++) bb[j] = bias[col0 + j];
#pragma unroll
    for (int i = 0; i < 4; i++) {
        float2 a0 = up2(acc2[i][0]), a1 = up2(acc2[i][1]);
        float2 a2 = up2(acc2[i][2]), a3 = up2(acc2[i][3]);
        float* yp = &Y[(size_t)(bm + row0 + i) * QKV_N + col0];
        *(float4*)yp = make_float4(a0.x + bb[0], a0.y + bb[1], a1.x + bb[2], a1.y + bb[3]);
        *(float4*)(yp + 4) = make_float4(a2.x + bb[4], a2.y + bb[5], a3.x + bb[6], a3.y + bb[7]);
    }
}

// ---- out-proj GEMM
__global__ __launch_bounds__(256) void gemm_bias_kernel(
    const float* __restrict__ X, const float* __restrict__ W,
    const float* __restrict__ bias, float* __restrict__ Y,
    int M, int K, int N)
{
    __shared__ float xs[32 * 68];
    __shared__ float ws[32 * 132];
    int tid = threadIdx.x;
    int tx = tid & 15, ty = tid >> 4;
    int bm = blockIdx.x * 64, bn = blockIdx.y * 128;
    int row0 = ty * 4, col0 = tx * 8;

    ull acc2[4][4];
#pragma unroll
    for (int i = 0; i < 4; i++)
#pragma unroll
        for (int j = 0; j < 4; j++) acc2[i][j] = 0ull;

    for (int k0 = 0; k0 < K; k0 += 32) {
#pragma unroll
        for (int i = 0; i < 2; i++) {
            int linear = tid + i * 256;
            int m = linear >> 3;
            int g = (linear & 7) * 4;
            float4 v = *(const float4*)&X[(size_t)(bm + m) * K + k0 + g];
            xs[(g + 0) * 68 + m] = v.x;
            xs[(g + 1) * 68 + m] = v.y;
            xs[(g + 2) * 68 + m] = v.z;
            xs[(g + 3) * 68 + m] = v.w;
        }
#pragma unroll
        for (int i = 0; i < 4; i++) {
            int linear = tid + i * 256;
            int k = linear >> 5;
            int g = (linear & 31) * 4;
            *(float4*)&ws[k * 132 + g] = *(const float4*)&W[(size_t)(k0 + k) * N + bn + g];
        }
        __syncthreads();
#pragma unroll
        for (int k = 0; k < 32; k++) {
            float4 xa = *(const float4*)&xs[k * 68 + row0];
            float4 wa = *(const float4*)&ws[k * 132 + col0];
            float4 wb = *(const float4*)&ws[k * 132 + col0 + 4];
            ull wp[4] = {pk2(wa.x, wa.y), pk2(wa.z, wa.w),
                         pk2(wb.x, wb.y), pk2(wb.z, wb.w)};
            ull xb[4] = {bc2(xa.x), bc2(xa.y), bc2(xa.z), bc2(xa.w)};
#pragma unroll
            for (int i = 0; i < 4; i++)
#pragma unroll
                for (int j = 0; j < 4; j++)
                    fma2(acc2[i][j], xb[i], wp[j]);
        }
        __syncthreads();
    }
    float bb[8];
#pragma unroll
    for (int j = 0; j < 8; j++) bb[j] = bias[bn + col0 + j];
#pragma unroll
    for (int i = 0; i < 4; i++) {
        float2 a0 = up2(acc2[i][0]), a1 = up2(acc2[i][1]);
        float2 a2 = up2(acc2[i][2]), a3 = up2(acc2[i][3]);
        float* yp = &Y[(size_t)(bm + row0 + i) * N + bn + col0];
        *(float4*)yp = make_float4(a0.x + bb[0], a0.y + bb[1], a1.x + bb[2], a1.y + bb[3]);
        *(float4*)(yp + 4) = make_float4(a2.x + bb[4], a2.y + bb[5], a3.x + bb[6], a3.y + bb[7]);
    }
}

__global__ void vsum_zero_kernel() { g_vsum[threadIdx.x] = 0.f; }

__global__ __launch_bounds__(256) void vsum_kernel()
{
    __shared__ float red[8][128];
    int b = blockIdx.x, part = blockIdx.y;
    int c4 = (threadIdx.x & 31) * 4;
    int r0 = threadIdx.x >> 5;
    const float* base = g_v + ((size_t)b * LK + part * 128) * QKV_N;
    float4 s = make_float4(0.f, 0.f, 0.f, 0.f);
#pragma unroll 4
    for (int r = r0; r < 128; r += 8) {
        float4 v = *(const float4*)&base[(size_t)r * QKV_N + c4];
        s.x += v.x; s.y += v.y; s.z += v.z; s.w += v.w;
    }
    *(float4*)&red[r0][c4] = s;
    __syncthreads();
    if (threadIdx.x < 128) {
        float t = 0.f;
#pragma unroll
        for (int i = 0; i < 8; i++) t += red[i][threadIdx.x];
        atomicAdd(&g_vsum[b * QKV_N + threadIdx.x], t);
    }
}

// streaming lse fix-up: attn[row][*] -= lse[row]; 2 rows per 256-thread block
__global__ __launch_bounds__(256) void lse_fix_kernel(float* __restrict__ attn)
{
    int row = blockIdx.x * 2 + (threadIdx.x >> 7);
    int lane = threadIdx.x & 127;
    float l = g_lse[row];
    float4* p = (float4*)(attn + (size_t)row * LK);
#pragma unroll
    for (int j = 0; j < 4; j++) {
        int idx = lane + j * 128;
        float4 a = p[idx];
        a.x -= l; a.y -= l; a.z -= l; a.w -= l;
        p[idx] = a;
    }
}

// one block = 128 queries for one (b,h); 256 threads; 8x8 QK frag, 8x4 SV frag
__global__ __launch_bounds__(256) void mab_main_kernel(
    const void* __restrict__ maskp, float* __restrict__ attn)
{
    extern __shared__ float sm[];
    int tid = threadIdx.x;
    int tx = tid & 15, ty = tid >> 4;
    int m0 = ty * 8;
    int nk = tx * 8;
    int nv = tx * 4;
    int q0 = blockIdx.x * BQ;
    int h = blockIdx.y, b = blockIdx.z;
    int mode = g_mask_mode;

    const float* qbase = g_q + ((size_t)b * LQ + q0) * QKV_N + h * DK;
#pragma unroll
    for (int i = 0; i < 8; i++) {
        int linear = tid + i * 256;
        int m = linear >> 4;
        int d = (linear & 15) * 4;
        float4 v = *(const float4*)&qbase[(size_t)m * QKV_N + d];
        sm[OFF_Q + (d + 0) * Q_STR + m] = v.x * 0.125f;
        sm[OFF_Q + (d + 1) * Q_STR + m] = v.y * 0.125f;
        sm[OFF_Q + (d + 2) * Q_STR + m] = v.z * 0.125f;
        sm[OFF_Q + (d + 3) * Q_STR + m] = v.w * 0.125f;
    }
    if (tid < BQ) sm[OFF_RL + tid] = 0.f;

    ull sv2[4][4];
#pragma unroll
    for (int i = 0; i < 4; i++)
#pragma unroll
        for (int j = 0; j < 4; j++) sv2[i][j] = 0ull;

    const float* kbase = g_k + (size_t)b * LK * QKV_N + h * DK;
    const float* vbase = g_v + (size_t)b * LK * QKV_N + h * DK;
    float* arow = attn + ((size_t)((b * NH + h) * LQ + q0)) * LK;

    __syncthreads();

    for (int c = 0; c < LK / BK; c++) {
        int k0 = c * BK;
        // V chunk via cp.async (natural layout, contiguous 16B)
#pragma unroll
        for (int i = 0; i < 8; i++) {
            int linear = tid + i * 256;
            int kr = linear >> 4;
            int d = (linear & 15) * 4;
            cp_async16(smem_u32(&sm[OFF_V + kr * DV + d]),
                       &vbase[(size_t)(k0 + kr) * QKV_N + d]);
        }
        cp_async_commit();
        // K chunk transposed [d][kr] (needs register staging)
#pragma unroll
        for (int i = 0; i < 8; i++) {
            int linear = tid + i * 256;
            int kr = linear >> 4;
            int d = (linear & 15) * 4;
            float4 v = *(const float4*)&kbase[(size_t)(k0 + kr) * QKV_N + d];
            sm[OFF_K + (d + 0) * K_STR + kr] = v.x;
            sm[OFF_K + (d + 1) * K_STR + kr] = v.y;
            sm[OFF_K + (d + 2) * K_STR + kr] = v.z;
            sm[OFF_K + (d + 3) * K_STR + kr] = v.w;
        }
        if (tid < BK) {
            size_t gi = (size_t)b * LK + k0 + tid;
            int mm;
            if (mode == 1)      mm = ((const int*)maskp)[gi] != 0;
            else if (mode == 0) mm = ((const unsigned char*)maskp)[gi] != 0;
            else                mm = ((const float*)maskp)[gi] != 0.f;
            sm[OFF_MSK + tid] = mm ? 1.f : 0.f;
        }
        cp_async_wait0();
        __syncthreads();

        // phase 1: S = q @ k^T, 8 queries x 8 keys per thread
        ull acc2[4][8];
#pragma unroll
        for (int p = 0; p < 4; p++)
#pragma unroll
            for (int j = 0; j < 8; j++) acc2[p][j] = 0ull;

#pragma unroll 4
        for (int d = 0; d < DK; d++) {
            float4 qa = *(const float4*)&sm[OFF_Q + d * Q_STR + m0];
            float4 qb = *(const float4*)&sm[OFF_Q + d * Q_STR + m0 + 4];
            float4 ka = *(const float4*)&sm[OFF_K + d * K_STR + nk];
            float4 kb4 = *(const float4*)&sm[OFF_K + d * K_STR + nk + 4];
            ull qp[4] = {pk2(qa.x, qa.y), pk2(qa.z, qa.w),
                         pk2(qb.x, qb.y), pk2(qb.z, qb.w)};
            ull kb[8] = {bc2(ka.x), bc2(ka.y), bc2(ka.z), bc2(ka.w),
                         bc2(kb4.x), bc2(kb4.y), bc2(kb4.z), bc2(kb4.w)};
#pragma unroll
            for (int p = 0; p < 4; p++)
#pragma unroll
                for (int j = 0; j < 8; j++)
                    fma2(acc2[p][j], qp[p], kb[j]);
        }

        float acc[8][8];
#pragma unroll
        for (int p = 0; p < 4; p++)
#pragma unroll
            for (int j = 0; j < 8; j++) {
                float2 v = up2(acc2[p][j]);
                acc[2 * p][j] = v.x;
                acc[2 * p + 1][j] = v.y;
            }

        float mk[8];
#pragma unroll
        for (int j = 0; j < 8; j++) mk[j] = sm[OFF_MSK + nk + j];

        float er[8];
#pragma unroll
        for (int i = 0; i < 8; i++) {
            float rs = 0.f;
#pragma unroll
            for (int j = 0; j < 8; j++) {
                float s = tanh10(acc[i][j]);
                if (mk[j] != 0.f) s = -10.f;
                acc[i][j] = s;
                rs += __expf(s);
            }
            er[i] = rs;
            float* ap = &arow[(size_t)(m0 + i) * LK + k0 + nk];
            *(float4*)ap = make_float4(acc[i][0], acc[i][1], acc[i][2], acc[i][3]);
            *(float4*)(ap + 4) = make_float4(acc[i][4], acc[i][5], acc[i][6], acc[i][7]);
        }
#pragma unroll
        for (int d = 1; d < 16; d <<= 1) {
#pragma unroll
            for (int i = 0; i < 8; i++)
                er[i] += __shfl_xor_sync(0xffffffffu, er[i], d);
        }
        if (tx == 0) {
#pragma unroll
            for (int i = 0; i < 8; i++)
                sm[OFF_RL + m0 + i] += er[i];
        }
        {
            int g = m0 >> 2;
#pragma unroll
            for (int j = 0; j < 8; j++) {
                int kc = nk + j;
                *(float4*)&sm[s_off(kc, g)] =
                    make_float4(acc[0][j], acc[1][j], acc[2][j], acc[3][j]);
                *(float4*)&sm[s_off(kc, g + 1)] =
                    make_float4(acc[4][j], acc[5][j], acc[6][j], acc[7][j]);
            }
        }
        __syncthreads();

        // phase 2: SV += S_chunk @ v_chunk (8 queries x 4 dv per thread)
        {
            int g = m0 >> 2;
#pragma unroll 8
            for (int kc = 0; kc < BK; kc++) {
                float4 sa = *(const float4*)&sm[s_off(kc, g)];
                float4 sb = *(const float4*)&sm[s_off(kc, g + 1)];
                float4 vv = *(const float4*)&sm[OFF_V + kc * DV + nv];
                ull sp[4] = {pk2(sa.x, sa.y), pk2(sa.z, sa.w),
                             pk2(sb.x, sb.y), pk2(sb.z, sb.w)};
                ull vb[4] = {bc2(vv.x), bc2(vv.y), bc2(vv.z), bc2(vv.w)};
#pragma unroll
                for (int p = 0; p < 4; p++)
#pragma unroll
                    for (int j = 0; j < 4; j++)
                        fma2(sv2[p][j], sp[p], vb[j]);
            }
        }
        __syncthreads();
    }

    if (tid < BQ) {
        float l = logf(sm[OFF_RL + tid]);
        sm[OFF_LSE + tid] = l;
        g_lse[(b * NH + h) * LQ + q0 + tid] = l;
    }
    __syncthreads();

    {   // otmp = SV - lse * vsum
        float4 vs = *(const float4*)&g_vsum[(b * NH + h) * DV + nv];
#pragma unroll
        for (int p = 0; p < 4; p++) {
            float2 c0 = up2(sv2[p][0]), c1 = up2(sv2[p][1]);
            float2 c2 = up2(sv2[p][2]), c3 = up2(sv2[p][3]);
            float l0 = sm[OFF_LSE + m0 + 2 * p];
            float l1 = sm[OFF_LSE + m0 + 2 * p + 1];
            size_t r0 = ((size_t)b * LQ + q0 + m0 + 2 * p) * QKV_N + h * DK + nv;
            *(float4*)&g_otmp[r0] =
                make_float4(c0.x - l0 * vs.x, c1.x - l0 * vs.y,
                            c2.x - l0 * vs.z, c3.x - l0 * vs.w);
            *(float4*)&g_otmp[r0 + QKV_N] =
                make_float4(c0.y - l1 * vs.x, c1.y - l1 * vs.y,
                            c2.y - l1 * vs.z, c3.y - l1 * vs.w);
        }
    }
}

extern "C" void kernel_launch(void* const* d_in, const int* in_sizes, int n_in,
                              void* d_out, int out_size)
{
    const float* Q  = (const float*)d_in[0];
    const float* K  = (const float*)d_in[1];
    const float* V  = (const float*)d_in[2];
    const void*  Mk = d_in[3];
    const float* Wq = (const float*)d_in[4];
    const float* bq = (const float*)d_in[5];
    const float* Wk = (const float*)d_in[6];
    const float* bk = (const float*)d_in[7];
    const float* Wv = (const float*)d_in[8];
    const float* bv = (const float*)d_in[9];
    const float* Wo = (const float*)d_in[10];
    const float* bo = (const float*)d_in[11];

    float* out  = (float*)d_out;
    float* attn = out + (size_t)BATCH * LQ * DMODEL;

    float *gq, *gk, *gv, *gotmp;
    cudaGetSymbolAddress((void**)&gq, g_q);
    cudaGetSymbolAddress((void**)&gk, g_k);
    cudaGetSymbolAddress((void**)&gv, g_v);
    cudaGetSymbolAddress((void**)&gotmp, g_otmp);

    static int smem_set = 0;
    if (!smem_set) {
        cudaFuncSetAttribute(mab_main_kernel,
                             cudaFuncAttributeMaxDynamicSharedMemorySize, SMEM_BYTES);
        smem_set = 1;
    }

    detect_mask_kernel<<<1, 256>>>((const unsigned int*)Mk);

    const int M = BATCH * LQ;  // 8192
    gemm_qkv_kernel<<<dim3(M / 64, 3), 256>>>(Q, K, V, Wq, Wk, Wv,
                                              bq, bk, bv, gq, gk, gv);

    vsum_zero_kernel<<<1, BATCH * QKV_N>>>();
    vsum_kernel<<<dim3(BATCH, 16), 256>>>();

    mab_main_kernel<<<dim3(LQ / BQ, NH, BATCH), 256, SMEM_BYTES>>>(Mk, attn);

    lse_fix_kernel<<<BATCH * NH * LQ / 2, 256>>>(attn);

    gemm_bias_kernel<<<dim3(M / 64, DMODEL / 128), 256>>>(gotmp, Wo, bo, out,
                                                          M, QKV_N, DMODEL);
}

// round 10
// speedup vs baseline: 1.1673x; 1.0779x over previous
#include <cuda_runtime.h>
#include <math.h>

#define BATCH 4
#define LQ 2048
#define LK 2048
#define DMODEL 512
#define NH 2
#define DK 64
#define DV 64
#define QKV_N 128

#define BQ 128
#define BK 128

// unpadded smem layout (floats)
#define OFF_Q 0
#define OFF_K0 8192
#define OFF_K1 16384
#define OFF_V0 24576
#define OFF_V1 32768
#define OFF_S 40960
#define OFF_RL 57344
#define OFF_LSE 57472
#define OFF_MSK 57600
#define SMEM_FLOATS 57728
#define SMEM_BYTES (SMEM_FLOATS * 4)   // 230912 < 232448 max

typedef unsigned long long ull;

__device__ __forceinline__ ull pk2(float x, float y)
{ ull r; asm("mov.b64 %0,{%1,%2};" : "=l"(r) : "f"(x), "f"(y)); return r; }
__device__ __forceinline__ ull bc2(float x) { return pk2(x, x); }
__device__ __forceinline__ void fma2(ull& d, ull a, ull b)
{ asm("fma.rn.f32x2 %0,%1,%2,%0;" : "+l"(d) : "l"(a), "l"(b)); }
__device__ __forceinline__ float2 up2(ull v)
{ float2 r; asm("mov.b64 {%0,%1},%2;" : "=f"(r.x), "=f"(r.y) : "l"(v)); return r; }

__device__ __forceinline__ unsigned smem_u32(const void* p)
{
    unsigned a;
    asm("{ .reg .u64 t; cvta.to.shared.u64 t, %1; cvt.u32.u64 %0, t; }"
        : "=r"(a) : "l"(p));
    return a;
}
__device__ __forceinline__ void cp_async16(unsigned dst, const void* src)
{ asm volatile("cp.async.cg.shared.global [%0],[%1],16;" :: "r"(dst), "l"(src)); }
__device__ __forceinline__ void cp_async_commit()
{ asm volatile("cp.async.commit_group;"); }
__device__ __forceinline__ void cp_async_wait0()
{ asm volatile("cp.async.wait_group 0;"); }
__device__ __forceinline__ void cp_async_wait1()
{ asm volatile("cp.async.wait_group 1;"); }

__device__ __forceinline__ int s_off(int kc, int g)
{ return OFF_S + kc * BQ + (((g + kc + (kc >> 3)) & 31) << 2); }

// 10*tanh(0.125*x) = 10 - 20/(exp(0.25x)+1); exact at +/-inf
__device__ __forceinline__ float tanh10s(float x)
{
    float e = __expf(0.25f * x);
    float r;
    asm("rcp.approx.f32 %0,%1;" : "=f"(r) : "f"(e + 1.f));
    return fmaf(-20.f, r, 10.f);
}

__device__ float g_qT[BATCH * QKV_N * LQ];   // [b*128 + col][l]
__device__ float g_kT[BATCH * QKV_N * LK];   // [b*128 + col][l]
__device__ float g_v[BATCH * LK * QKV_N];    // natural
__device__ float g_otmp[BATCH * LQ * QKV_N];
__device__ float g_vsum[BATCH * QKV_N];
__device__ float g_lse[BATCH * NH * LQ];
__device__ int g_mask_mode;  // 0=u8, 1=i32, 2=f32

__device__ __forceinline__ float mask_at(const void* p, int mode, size_t gi)
{
    if (mode == 1) return ((const int*)p)[gi] != 0 ? 1.f : 0.f;
    if (mode == 0) return ((const unsigned char*)p)[gi] != 0 ? 1.f : 0.f;
    return ((const float*)p)[gi] != 0.f ? 1.f : 0.f;
}

__global__ void detect_mask_kernel(const unsigned int* __restrict__ w)
{
    __shared__ int s_f32, s_all01;
    if (threadIdx.x == 0) { s_f32 = 0; s_all01 = 1; }
    __syncthreads();
    int f = 0, bad = 0;
    for (int i = threadIdx.x; i < 2048; i += blockDim.x) {
        unsigned v = w[i];
        if (v == 0x3F800000u) f = 1;
        if (v > 1u) bad = 1;
    }
    if (f) atomicOr(&s_f32, 1);
    if (bad) atomicExch(&s_all01, 0);
    __syncthreads();
    if (threadIdx.x == 0) g_mask_mode = s_f32 ? 2 : (s_all01 ? 1 : 0);
}

// ---- fused QKV projection: 128x128 tile, 8x8 frags.
// sel 0 (Q) and 1 (K) write TRANSPOSED output [b*128+col][l]; sel 2 (V) natural.
__global__ __launch_bounds__(256) void gemm_qkv_kernel(
    const float* __restrict__ X0, const float* __restrict__ X1, const float* __restrict__ X2,
    const float* __restrict__ W0, const float* __restrict__ W1, const float* __restrict__ W2,
    const float* __restrict__ B0, const float* __restrict__ B1, const float* __restrict__ B2,
    float* __restrict__ Y0, float* __restrict__ Y1, float* __restrict__ Y2)
{
    __shared__ float xs[32 * 132];
    __shared__ float ws[32 * 132];
    int sel = blockIdx.y;
    const float* X = sel == 0 ? X0 : (sel == 1 ? X1 : X2);
    const float* W = sel == 0 ? W0 : (sel == 1 ? W1 : W2);
    const float* bias = sel == 0 ? B0 : (sel == 1 ? B1 : B2);
    float* Y = sel == 0 ? Y0 : (sel == 1 ? Y1 : Y2);

    int tid = threadIdx.x;
    int tx = tid & 15, ty = tid >> 4;
    int bm = blockIdx.x * 128;
    int row0 = ty * 8, col0 = tx * 8;

    ull acc2[4][8];
#pragma unroll
    for (int p = 0; p < 4; p++)
#pragma unroll
        for (int j = 0; j < 8; j++) acc2[p][j] = 0ull;

    for (int k0 = 0; k0 < DMODEL; k0 += 32) {
#pragma unroll
        for (int i = 0; i < 4; i++) {
            int linear = tid + i * 256;
            int m = linear >> 3;
            int g = (linear & 7) * 4;
            float4 v = *(const float4*)&X[(size_t)(bm + m) * DMODEL + k0 + g];
            xs[(g + 0) * 132 + m] = v.x;
            xs[(g + 1) * 132 + m] = v.y;
            xs[(g + 2) * 132 + m] = v.z;
            xs[(g + 3) * 132 + m] = v.w;
        }
#pragma unroll
        for (int i = 0; i < 4; i++) {
            int linear = tid + i * 256;
            int k = linear >> 5;
            int g = (linear & 31) * 4;
            *(float4*)&ws[k * 132 + g] = *(const float4*)&W[(size_t)(k0 + k) * QKV_N + g];
        }
        __syncthreads();
#pragma unroll
        for (int k = 0; k < 32; k++) {
            float4 xa = *(const float4*)&xs[k * 132 + row0];
            float4 xb = *(const float4*)&xs[k * 132 + row0 + 4];
            float4 wa = *(const float4*)&ws[k * 132 + col0];
            float4 wb = *(const float4*)&ws[k * 132 + col0 + 4];
            ull xp[4] = {pk2(xa.x, xa.y), pk2(xa.z, xa.w),
                         pk2(xb.x, xb.y), pk2(xb.z, xb.w)};
            ull wn[8] = {bc2(wa.x), bc2(wa.y), bc2(wa.z), bc2(wa.w),
                         bc2(wb.x), bc2(wb.y), bc2(wb.z), bc2(wb.w)};
#pragma unroll
            for (int p = 0; p < 4; p++)
#pragma unroll
                for (int j = 0; j < 8; j++)
                    fma2(acc2[p][j], xp[p], wn[j]);
        }
        __syncthreads();
    }
    float bb[8];
#pragma unroll
    for (int j = 0; j < 8; j++) bb[j] = bias[col0 + j];

    if (sel == 2) {  // natural store
#pragma unroll
        for (int p = 0; p < 4; p++) {
            float r0[8], r1[8];
#pragma unroll
            for (int j = 0; j < 8; j++) {
                float2 t = up2(acc2[p][j]);
                r0[j] = t.x + bb[j];
                r1[j] = t.y + bb[j];
            }
            float* y0 = &Y[(size_t)(bm + row0 + 2 * p) * QKV_N + col0];
            *(float4*)y0 = make_float4(r0[0], r0[1], r0[2], r0[3]);
            *(float4*)(y0 + 4) = make_float4(r0[4], r0[5], r0[6], r0[7]);
            float* y1 = y0 + QKV_N;
            *(float4*)y1 = make_float4(r1[0], r1[1], r1[2], r1[3]);
            *(float4*)(y1 + 4) = make_float4(r1[4], r1[5], r1[6], r1[7]);
        }
    } else {  // transposed store: Y[(b*128+col)*2048 + l]
        int b = bm >> 11;
        int l0 = (bm & 2047) + row0;
#pragma unroll
        for (int j = 0; j < 8; j++) {
            float v[8];
#pragma unroll
            for (int p = 0; p < 4; p++) {
                float2 t = up2(acc2[p][j]);
                v[2 * p] = t.x + bb[j];
                v[2 * p + 1] = t.y + bb[j];
            }
            float* yp = &Y[((size_t)(b * QKV_N + col0 + j)) * LQ + l0];
            *(float4*)yp = make_float4(v[0], v[1], v[2], v[3]);
            *(float4*)(yp + 4) = make_float4(v[4], v[5], v[6], v[7]);
        }
    }
}

// ---- out-proj GEMM (64x128 tile, unchanged)
__global__ __launch_bounds__(256) void gemm_bias_kernel(
    const float* __restrict__ X, const float* __restrict__ W,
    const float* __restrict__ bias, float* __restrict__ Y,
    int M, int K, int N)
{
    __shared__ float xs[32 * 68];
    __shared__ float ws[32 * 132];
    int tid = threadIdx.x;
    int tx = tid & 15, ty = tid >> 4;
    int bm = blockIdx.x * 64, bn = blockIdx.y * 128;
    int row0 = ty * 4, col0 = tx * 8;

    ull acc2[4][4];
#pragma unroll
    for (int i = 0; i < 4; i++)
#pragma unroll
        for (int j = 0; j < 4; j++) acc2[i][j] = 0ull;

    for (int k0 = 0; k0 < K; k0 += 32) {
#pragma unroll
        for (int i = 0; i < 2; i++) {
            int linear = tid + i * 256;
            int m = linear >> 3;
            int g = (linear & 7) * 4;
            float4 v = *(const float4*)&X[(size_t)(bm + m) * K + k0 + g];
            xs[(g + 0) * 68 + m] = v.x;
            xs[(g + 1) * 68 + m] = v.y;
            xs[(g + 2) * 68 + m] = v.z;
            xs[(g + 3) * 68 + m] = v.w;
        }
#pragma unroll
        for (int i = 0; i < 4; i++) {
            int linear = tid + i * 256;
            int k = linear >> 5;
            int g = (linear & 31) * 4;
            *(float4*)&ws[k * 132 + g] = *(const float4*)&W[(size_t)(k0 + k) * N + bn + g];
        }
        __syncthreads();
#pragma unroll
        for (int k = 0; k < 32; k++) {
            float4 xa = *(const float4*)&xs[k * 68 + row0];
            float4 wa = *(const float4*)&ws[k * 132 + col0];
            float4 wb = *(const float4*)&ws[k * 132 + col0 + 4];
            ull wp[4] = {pk2(wa.x, wa.y), pk2(wa.z, wa.w),
                         pk2(wb.x, wb.y), pk2(wb.z, wb.w)};
            ull xb[4] = {bc2(xa.x), bc2(xa.y), bc2(xa.z), bc2(xa.w)};
#pragma unroll
            for (int i = 0; i < 4; i++)
#pragma unroll
                for (int j = 0; j < 4; j++)
                    fma2(acc2[i][j], xb[i], wp[j]);
        }
        __syncthreads();
    }
    float bb[8];
#pragma unroll
    for (int j = 0; j < 8; j++) bb[j] = bias[bn + col0 + j];
#pragma unroll
    for (int i = 0; i < 4; i++) {
        float2 a0 = up2(acc2[i][0]), a1 = up2(acc2[i][1]);
        float2 a2 = up2(acc2[i][2]), a3 = up2(acc2[i][3]);
        float* yp = &Y[(size_t)(bm + row0 + i) * N + bn + col0];
        *(float4*)yp = make_float4(a0.x + bb[0], a0.y + bb[1], a1.x + bb[2], a1.y + bb[3]);
        *(float4*)(yp + 4) = make_float4(a2.x + bb[4], a2.y + bb[5], a3.x + bb[6], a3.y + bb[7]);
    }
}

__global__ void vsum_zero_kernel() { g_vsum[threadIdx.x] = 0.f; }

__global__ __launch_bounds__(256) void vsum_kernel()
{
    __shared__ float red[8][128];
    int b = blockIdx.x, part = blockIdx.y;
    int c4 = (threadIdx.x & 31) * 4;
    int r0 = threadIdx.x >> 5;
    const float* base = g_v + ((size_t)b * LK + part * 128) * QKV_N;
    float4 s = make_float4(0.f, 0.f, 0.f, 0.f);
#pragma unroll 4
    for (int r = r0; r < 128; r += 8) {
        float4 v = *(const float4*)&base[(size_t)r * QKV_N + c4];
        s.x += v.x; s.y += v.y; s.z += v.z; s.w += v.w;
    }
    *(float4*)&red[r0][c4] = s;
    __syncthreads();
    if (threadIdx.x < 128) {
        float t = 0.f;
#pragma unroll
        for (int i = 0; i < 8; i++) t += red[i][threadIdx.x];
        atomicAdd(&g_vsum[b * QKV_N + threadIdx.x], t);
    }
}

// streaming lse fix-up: attn[row][*] -= lse[row]; 2 rows per block
__global__ __launch_bounds__(256) void lse_fix_kernel(float* __restrict__ attn)
{
    int row = blockIdx.x * 2 + (threadIdx.x >> 7);
    int lane = threadIdx.x & 127;
    float l = g_lse[row];
    float4* p = (float4*)(attn + (size_t)row * LK);
#pragma unroll
    for (int j = 0; j < 4; j++) {
        int idx = lane + j * 128;
        float4 a = p[idx];
        a.x -= l; a.y -= l; a.z -= l; a.w -= l;
        p[idx] = a;
    }
}

// one block = 128 queries for one (b,h); double-buffered cp.async K/V pipeline
__global__ __launch_bounds__(256) void mab_main_kernel(
    const void* __restrict__ maskp, float* __restrict__ attn)
{
    extern __shared__ float sm[];
    int tid = threadIdx.x;
    int tx = tid & 15, ty = tid >> 4;
    int m0 = ty * 8;
    int nk = tx * 8;
    int nv = tx * 4;
    int q0 = blockIdx.x * BQ;
    int h = blockIdx.y, b = blockIdx.z;
    int mode = g_mask_mode;

    const float* qtbase = g_qT + ((size_t)(b * QKV_N + h * DK)) * LQ + q0;
    const float* ktbase = g_kT + ((size_t)(b * QKV_N + h * DK)) * LK;
    const float* vbase  = g_v + (size_t)b * LK * QKV_N + h * DK;
    float* arow = attn + ((size_t)((b * NH + h) * LQ + q0)) * LK;

    // prologue: Q tile + K(0) + V(0) via cp.async (one group)
#pragma unroll
    for (int i = 0; i < 8; i++) {
        int lin = tid + i * 256;
        int d = lin >> 5, qq = (lin & 31) * 4;
        cp_async16(smem_u32(&sm[OFF_Q + d * 128 + qq]), &qtbase[(size_t)d * LQ + qq]);
    }
#pragma unroll
    for (int i = 0; i < 8; i++) {
        int lin = tid + i * 256;
        int d = lin >> 5, kk = (lin & 31) * 4;
        cp_async16(smem_u32(&sm[OFF_K0 + d * 128 + kk]), &ktbase[(size_t)d * LK + kk]);
    }
#pragma unroll
    for (int i = 0; i < 8; i++) {
        int lin = tid + i * 256;
        int kr = lin >> 4, dv = (lin & 15) * 4;
        cp_async16(smem_u32(&sm[OFF_V0 + kr * DV + dv]), &vbase[(size_t)kr * QKV_N + dv]);
    }
    cp_async_commit();
    float mreg = 0.f;
    if (tid < BK) mreg = mask_at(maskp, mode, (size_t)b * LK + tid);
    if (tid < BQ) sm[OFF_RL + tid] = 0.f;

    ull sv2[4][4];
#pragma unroll
    for (int i = 0; i < 4; i++)
#pragma unroll
        for (int j = 0; j < 4; j++) sv2[i][j] = 0ull;

    for (int c = 0; c < LK / BK; c++) {
        int k0 = c * BK;
        int kbuf = (c & 1) ? OFF_K1 : OFF_K0;
        int vbuf = (c & 1) ? OFF_V1 : OFF_V0;
        __syncthreads();   // prev phase2 done -> other buffers free
        if (tid < BK) sm[OFF_MSK + tid] = mreg;
        if (c < 15) {
            int k1 = k0 + BK;
            int kb2 = (c & 1) ? OFF_K0 : OFF_K1;
            int vb2 = (c & 1) ? OFF_V0 : OFF_V1;
#pragma unroll
            for (int i = 0; i < 8; i++) {
                int lin = tid + i * 256;
                int d = lin >> 5, kk = (lin & 31) * 4;
                cp_async16(smem_u32(&sm[kb2 + d * 128 + kk]),
                           &ktbase[(size_t)d * LK + k1 + kk]);
            }
#pragma unroll
            for (int i = 0; i < 8; i++) {
                int lin = tid + i * 256;
                int kr = lin >> 4, dv = (lin & 15) * 4;
                cp_async16(smem_u32(&sm[vb2 + kr * DV + dv]),
                           &vbase[(size_t)(k1 + kr) * QKV_N + dv]);
            }
            cp_async_commit();
            if (tid < BK) mreg = mask_at(maskp, mode, (size_t)b * LK + k1 + tid);
            cp_async_wait1();
        } else {
            cp_async_wait0();
        }
        __syncthreads();   // K(c)/V(c)/mask visible

        // phase 1: S = q @ k^T, 8 queries x 8 keys per thread
        ull acc2[4][8];
#pragma unroll
        for (int p = 0; p < 4; p++)
#pragma unroll
            for (int j = 0; j < 8; j++) acc2[p][j] = 0ull;

#pragma unroll 4
        for (int d = 0; d < DK; d++) {
            float4 qa = *(const float4*)&sm[OFF_Q + d * 128 + m0];
            float4 qb = *(const float4*)&sm[OFF_Q + d * 128 + m0 + 4];
            float4 ka = *(const float4*)&sm[kbuf + d * 128 + nk];
            float4 kb4 = *(const float4*)&sm[kbuf + d * 128 + nk + 4];
            ull qp[4] = {pk2(qa.x, qa.y), pk2(qa.z, qa.w),
                         pk2(qb.x, qb.y), pk2(qb.z, qb.w)};
            ull kb[8] = {bc2(ka.x), bc2(ka.y), bc2(ka.z), bc2(ka.w),
                         bc2(kb4.x), bc2(kb4.y), bc2(kb4.z), bc2(kb4.w)};
#pragma unroll
            for (int p = 0; p < 4; p++)
#pragma unroll
                for (int j = 0; j < 8; j++)
                    fma2(acc2[p][j], qp[p], kb[j]);
        }

        float acc[8][8];
#pragma unroll
        for (int p = 0; p < 4; p++)
#pragma unroll
            for (int j = 0; j < 8; j++) {
                float2 v = up2(acc2[p][j]);
                acc[2 * p][j] = v.x;
                acc[2 * p + 1][j] = v.y;
            }

        float mk[8];
#pragma unroll
        for (int j = 0; j < 8; j++) mk[j] = sm[OFF_MSK + nk + j];

        float er[8];
#pragma unroll
        for (int i = 0; i < 8; i++) {
            float rs = 0.f;
#pragma unroll
            for (int j = 0; j < 8; j++) {
                float s = tanh10s(acc[i][j]);   // scale 1/8 folded in
                if (mk[j] != 0.f) s = -10.f;
                acc[i][j] = s;
                rs += __expf(s);
            }
            er[i] = rs;
            float* ap = &arow[(size_t)(m0 + i) * LK + k0 + nk];
            *(float4*)ap = make_float4(acc[i][0], acc[i][1], acc[i][2], acc[i][3]);
            *(float4*)(ap + 4) = make_float4(acc[i][4], acc[i][5], acc[i][6], acc[i][7]);
        }
#pragma unroll
        for (int d = 1; d < 16; d <<= 1) {
#pragma unroll
            for (int i = 0; i < 8; i++)
                er[i] += __shfl_xor_sync(0xffffffffu, er[i], d);
        }
        if (tx == 0) {
#pragma unroll
            for (int i = 0; i < 8; i++)
                sm[OFF_RL + m0 + i] += er[i];
        }
        {
            int g = m0 >> 2;
#pragma unroll
            for (int j = 0; j < 8; j++) {
                int kc = nk + j;
                *(float4*)&sm[s_off(kc, g)] =
                    make_float4(acc[0][j], acc[1][j], acc[2][j], acc[3][j]);
                *(float4*)&sm[s_off(kc, g + 1)] =
                    make_float4(acc[4][j], acc[5][j], acc[6][j], acc[7][j]);
            }
        }
        __syncthreads();   // S visible

        // phase 2: SV += S_chunk @ v_chunk (8 queries x 4 dv per thread)
        {
            int g = m0 >> 2;
#pragma unroll 8
            for (int kc = 0; kc < BK; kc++) {
                float4 sa = *(const float4*)&sm[s_off(kc, g)];
                float4 sb = *(const float4*)&sm[s_off(kc, g + 1)];
                float4 vv = *(const float4*)&sm[vbuf + kc * DV + nv];
                ull sp[4] = {pk2(sa.x, sa.y), pk2(sa.z, sa.w),
                             pk2(sb.x, sb.y), pk2(sb.z, sb.w)};
                ull vb[4] = {bc2(vv.x), bc2(vv.y), bc2(vv.z), bc2(vv.w)};
#pragma unroll
                for (int p = 0; p < 4; p++)
#pragma unroll
                    for (int j = 0; j < 4; j++)
                        fma2(sv2[p][j], sp[p], vb[j]);
            }
        }
    }

    if (tid < BQ) {
        float l = logf(sm[OFF_RL + tid]);
        sm[OFF_LSE + tid] = l;
        g_lse[(b * NH + h) * LQ + q0 + tid] = l;
    }
    __syncthreads();

    {   // otmp = SV - lse * vsum
        float4 vs = *(const float4*)&g_vsum[(b * NH + h) * DV + nv];
#pragma unroll
        for (int p = 0; p < 4; p++) {
            float2 c0 = up2(sv2[p][0]), c1 = up2(sv2[p][1]);
            float2 c2 = up2(sv2[p][2]), c3 = up2(sv2[p][3]);
            float l0 = sm[OFF_LSE + m0 + 2 * p];
            float l1 = sm[OFF_LSE + m0 + 2 * p + 1];
            size_t r0 = ((size_t)b * LQ + q0 + m0 + 2 * p) * QKV_N + h * DK + nv;
            *(float4*)&g_otmp[r0] =
                make_float4(c0.x - l0 * vs.x, c1.x - l0 * vs.y,
                            c2.x - l0 * vs.z, c3.x - l0 * vs.w);
            *(float4*)&g_otmp[r0 + QKV_N] =
                make_float4(c0.y - l1 * vs.x, c1.y - l1 * vs.y,
                            c2.y - l1 * vs.z, c3.y - l1 * vs.w);
        }
    }
}

extern "C" void kernel_launch(void* const* d_in, const int* in_sizes, int n_in,
                              void* d_out, int out_size)
{
    const float* Q  = (const float*)d_in[0];
    const float* K  = (const float*)d_in[1];
    const float* V  = (const float*)d_in[2];
    const void*  Mk = d_in[3];
    const float* Wq = (const float*)d_in[4];
    const float* bq = (const float*)d_in[5];
    const float* Wk = (const float*)d_in[6];
    const float* bk = (const float*)d_in[7];
    const float* Wv = (const float*)d_in[8];
    const float* bv = (const float*)d_in[9];
    const float* Wo = (const float*)d_in[10];
    const float* bo = (const float*)d_in[11];

    float* out  = (float*)d_out;
    float* attn = out + (size_t)BATCH * LQ * DMODEL;

    float *gqt, *gkt, *gv, *gotmp;
    cudaGetSymbolAddress((void**)&gqt, g_qT);
    cudaGetSymbolAddress((void**)&gkt, g_kT);
    cudaGetSymbolAddress((void**)&gv, g_v);
    cudaGetSymbolAddress((void**)&gotmp, g_otmp);

    static int smem_set = 0;
    if (!smem_set) {
        cudaFuncSetAttribute(mab_main_kernel,
                             cudaFuncAttributeMaxDynamicSharedMemorySize, SMEM_BYTES);
        smem_set = 1;
    }

    detect_mask_kernel<<<1, 256>>>((const unsigned int*)Mk);

    const int M = BATCH * LQ;  // 8192
    gemm_qkv_kernel<<<dim3(M / 128, 3), 256>>>(Q, K, V, Wq, Wk, Wv,
                                               bq, bk, bv, gqt, gkt, gv);

    vsum_zero_kernel<<<1, BATCH * QKV_N>>>();
    vsum_kernel<<<dim3(BATCH, 16), 256>>>();

    mab_main_kernel<<<dim3(LQ / BQ, NH, BATCH), 256, SMEM_BYTES>>>(Mk, attn);

    lse_fix_kernel<<<BATCH * NH * LQ / 2, 256>>>(attn);

    gemm_bias_kernel<<<dim3(M / 64, DMODEL / 128), 256>>>(gotmp, Wo, bo, out,
                                                          M, QKV_N, DMODEL);
}

// round 12
// speedup vs baseline: 1.2245x; 1.0490x over previous
#include <cuda_runtime.h>
#include <math.h>

#define BATCH 4
#define LQ 2048
#define LK 2048
#define DMODEL 512
#define NH 2
#define DK 64
#define DV 64
#define QKV_N 128

#define BQ 128
#define BK 128

// unpadded smem layout (floats)
#define OFF_Q 0
#define OFF_K0 8192
#define OFF_K1 16384
#define OFF_V0 24576
#define OFF_V1 32768
#define OFF_S 40960
#define OFF_RL 57344
#define OFF_LSE 57472
#define OFF_MSK 57600      // double-buffered mask: 2 x 128
#define SMEM_FLOATS 57856
#define SMEM_BYTES (SMEM_FLOATS * 4)   // 231424 <= 232448 max

typedef unsigned long long ull;

__device__ __forceinline__ ull pk2(float x, float y)
{ ull r; asm("mov.b64 %0,{%1,%2};" : "=l"(r) : "f"(x), "f"(y)); return r; }
__device__ __forceinline__ ull bc2(float x) { return pk2(x, x); }
__device__ __forceinline__ void fma2(ull& d, ull a, ull b)
{ asm("fma.rn.f32x2 %0,%1,%2,%0;" : "+l"(d) : "l"(a), "l"(b)); }
__device__ __forceinline__ float2 up2(ull v)
{ float2 r; asm("mov.b64 {%0,%1},%2;" : "=f"(r.x), "=f"(r.y) : "l"(v)); return r; }

__device__ __forceinline__ unsigned smem_u32(const void* p)
{
    unsigned a;
    asm("{ .reg .u64 t; cvta.to.shared.u64 t, %1; cvt.u32.u64 %0, t; }"
        : "=r"(a) : "l"(p));
    return a;
}
__device__ __forceinline__ void cp_async16(unsigned dst, const void* src)
{ asm volatile("cp.async.cg.shared.global [%0],[%1],16;" :: "r"(dst), "l"(src)); }
__device__ __forceinline__ void cp_commit()
{ asm volatile("cp.async.commit_group;"); }
__device__ __forceinline__ void cp_wait0()
{ asm volatile("cp.async.wait_group 0;"); }

__device__ __forceinline__ void st_cs4(float* p, float4 v)
{ asm volatile("st.global.cs.v4.f32 [%0],{%1,%2,%3,%4};"
               :: "l"(p), "f"(v.x), "f"(v.y), "f"(v.z), "f"(v.w) : "memory"); }
__device__ __forceinline__ float4 ld_cs4(const float* p)
{
    float4 v;
    asm volatile("ld.global.cs.v4.f32 {%0,%1,%2,%3},[%4];"
                 : "=f"(v.x), "=f"(v.y), "=f"(v.z), "=f"(v.w) : "l"(p));
    return v;
}

__device__ __forceinline__ int s_off(int kc, int g)
{ return OFF_S + kc * BQ + (((g + kc + (kc >> 3)) & 31) << 2); }

// 10*tanh(0.125*x) = 10 - 20/(exp(0.25x)+1); exact at +/-inf
__device__ __forceinline__ float tanh10s(float x)
{
    float e = __expf(0.25f * x);
    float r;
    asm("rcp.approx.f32 %0,%1;" : "=f"(r) : "f"(e + 1.f));
    return fmaf(-20.f, r, 10.f);
}

__device__ float g_qT[BATCH * QKV_N * LQ];   // [b*128 + col][l]
__device__ float g_kT[BATCH * QKV_N * LK];   // [b*128 + col][l]
__device__ float g_v[BATCH * LK * QKV_N];    // natural
__device__ float g_otmp[BATCH * LQ * QKV_N];
__device__ float g_vsum[BATCH * QKV_N];
__device__ float g_lse[BATCH * NH * LQ];
__device__ int g_mask_mode;  // 0=u8, 1=i32, 2=f32

__device__ __forceinline__ float mask_at(const void* p, int mode, size_t gi)
{
    if (mode == 1) return ((const int*)p)[gi] != 0 ? 1.f : 0.f;
    if (mode == 0) return ((const unsigned char*)p)[gi] != 0 ? 1.f : 0.f;
    return ((const float*)p)[gi] != 0.f ? 1.f : 0.f;
}

__global__ void detect_mask_kernel(const unsigned int* __restrict__ w)
{
    __shared__ int s_f32, s_all01;
    if (threadIdx.x == 0) { s_f32 = 0; s_all01 = 1; }
    __syncthreads();
    int f = 0, bad = 0;
    for (int i = threadIdx.x; i < 2048; i += blockDim.x) {
        unsigned v = w[i];
        if (v == 0x3F800000u) f = 1;
        if (v > 1u) bad = 1;
    }
    if (f) atomicOr(&s_f32, 1);
    if (bad) atomicExch(&s_all01, 0);
    __syncthreads();
    if (threadIdx.x == 0) g_mask_mode = s_f32 ? 2 : (s_all01 ? 1 : 0);
}

// ---- fused QKV projection: 128x128 tile, 8x8 frags.
// sel 0 (Q) and 1 (K) write TRANSPOSED output [b*128+col][l]; sel 2 (V) natural.
__global__ __launch_bounds__(256) void gemm_qkv_kernel(
    const float* __restrict__ X0, const float* __restrict__ X1, const float* __restrict__ X2,
    const float* __restrict__ W0, const float* __restrict__ W1, const float* __restrict__ W2,
    const float* __restrict__ B0, const float* __restrict__ B1, const float* __restrict__ B2,
    float* __restrict__ Y0, float* __restrict__ Y1, float* __restrict__ Y2)
{
    __shared__ float xs[32 * 132];
    __shared__ float ws[32 * 132];
    int sel = blockIdx.y;
    const float* X = sel == 0 ? X0 : (sel == 1 ? X1 : X2);
    const float* W = sel == 0 ? W0 : (sel == 1 ? W1 : W2);
    const float* bias = sel == 0 ? B0 : (sel == 1 ? B1 : B2);
    float* Y = sel == 0 ? Y0 : (sel == 1 ? Y1 : Y2);

    int tid = threadIdx.x;
    int tx = tid & 15, ty = tid >> 4;
    int bm = blockIdx.x * 128;
    int row0 = ty * 8, col0 = tx * 8;

    ull acc2[4][8];
#pragma unroll
    for (int p = 0; p < 4; p++)
#pragma unroll
        for (int j = 0; j < 8; j++) acc2[p][j] = 0ull;

    for (int k0 = 0; k0 < DMODEL; k0 += 32) {
#pragma unroll
        for (int i = 0; i < 4; i++) {
            int linear = tid + i * 256;
            int m = linear >> 3;
            int g = (linear & 7) * 4;
            float4 v = *(const float4*)&X[(size_t)(bm + m) * DMODEL + k0 + g];
            xs[(g + 0) * 132 + m] = v.x;
            xs[(g + 1) * 132 + m] = v.y;
            xs[(g + 2) * 132 + m] = v.z;
            xs[(g + 3) * 132 + m] = v.w;
        }
#pragma unroll
        for (int i = 0; i < 4; i++) {
            int linear = tid + i * 256;
            int k = linear >> 5;
            int g = (linear & 31) * 4;
            *(float4*)&ws[k * 132 + g] = *(const float4*)&W[(size_t)(k0 + k) * QKV_N + g];
        }
        __syncthreads();
#pragma unroll
        for (int k = 0; k < 32; k++) {
            float4 xa = *(const float4*)&xs[k * 132 + row0];
            float4 xb = *(const float4*)&xs[k * 132 + row0 + 4];
            float4 wa = *(const float4*)&ws[k * 132 + col0];
            float4 wb = *(const float4*)&ws[k * 132 + col0 + 4];
            ull xp[4] = {pk2(xa.x, xa.y), pk2(xa.z, xa.w),
                         pk2(xb.x, xb.y), pk2(xb.z, xb.w)};
            ull wn[8] = {bc2(wa.x), bc2(wa.y), bc2(wa.z), bc2(wa.w),
                         bc2(wb.x), bc2(wb.y), bc2(wb.z), bc2(wb.w)};
#pragma unroll
            for (int p = 0; p < 4; p++)
#pragma unroll
                for (int j = 0; j < 8; j++)
                    fma2(acc2[p][j], xp[p], wn[j]);
        }
        __syncthreads();
    }
    float bb[8];
#pragma unroll
    for (int j = 0; j < 8; j++) bb[j] = bias[col0 + j];

    if (sel == 2) {
#pragma unroll
        for (int p = 0; p < 4; p++) {
            float r0[8], r1[8];
#pragma unroll
            for (int j = 0; j < 8; j++) {
                float2 t = up2(acc2[p][j]);
                r0[j] = t.x + bb[j];
                r1[j] = t.y + bb[j];
            }
            float* y0 = &Y[(size_t)(bm + row0 + 2 * p) * QKV_N + col0];
            *(float4*)y0 = make_float4(r0[0], r0[1], r0[2], r0[3]);
            *(float4*)(y0 + 4) = make_float4(r0[4], r0[5], r0[6], r0[7]);
            float* y1 = y0 + QKV_N;
            *(float4*)y1 = make_float4(r1[0], r1[1], r1[2], r1[3]);
            *(float4*)(y1 + 4) = make_float4(r1[4], r1[5], r1[6], r1[7]);
        }
    } else {
        int b = bm >> 11;
        int l0 = (bm & 2047) + row0;
#pragma unroll
        for (int j = 0; j < 8; j++) {
            float v[8];
#pragma unroll
            for (int p = 0; p < 4; p++) {
                float2 t = up2(acc2[p][j]);
                v[2 * p] = t.x + bb[j];
                v[2 * p + 1] = t.y + bb[j];
            }
            float* yp = &Y[((size_t)(b * QKV_N + col0 + j)) * LQ + l0];
            *(float4*)yp = make_float4(v[0], v[1], v[2], v[3]);
            *(float4*)(yp + 4) = make_float4(v[4], v[5], v[6], v[7]);
        }
    }
}

// ---- out-proj GEMM, 128x128 tile, 8x8 frags
__global__ __launch_bounds__(256) void gemm_bias128_kernel(
    const float* __restrict__ X, const float* __restrict__ W,
    const float* __restrict__ bias, float* __restrict__ Y,
    int M, int K, int N)
{
    __shared__ float xs[32 * 132];
    __shared__ float ws[32 * 132];
    int tid = threadIdx.x;
    int tx = tid & 15, ty = tid >> 4;
    int bm = blockIdx.x * 128, bn = blockIdx.y * 128;
    int row0 = ty * 8, col0 = tx * 8;

    ull acc2[4][8];
#pragma unroll
    for (int p = 0; p < 4; p++)
#pragma unroll
        for (int j = 0; j < 8; j++) acc2[p][j] = 0ull;

    for (int k0 = 0; k0 < K; k0 += 32) {
#pragma unroll
        for (int i = 0; i < 4; i++) {
            int linear = tid + i * 256;
            int m = linear >> 3;
            int g = (linear & 7) * 4;
            float4 v = *(const float4*)&X[(size_t)(bm + m) * K + k0 + g];
            xs[(g + 0) * 132 + m] = v.x;
            xs[(g + 1) * 132 + m] = v.y;
            xs[(g + 2) * 132 + m] = v.z;
            xs[(g + 3) * 132 + m] = v.w;
        }
#pragma unroll
        for (int i = 0; i < 4; i++) {
            int linear = tid + i * 256;
            int k = linear >> 5;
            int g = (linear & 31) * 4;
            *(float4*)&ws[k * 132 + g] = *(const float4*)&W[(size_t)(k0 + k) * N + bn + g];
        }
        __syncthreads();
#pragma unroll
        for (int k = 0; k < 32; k++) {
            float4 xa = *(const float4*)&xs[k * 132 + row0];
            float4 xb = *(const float4*)&xs[k * 132 + row0 + 4];
            float4 wa = *(const float4*)&ws[k * 132 + col0];
            float4 wb = *(const float4*)&ws[k * 132 + col0 + 4];
            ull xp[4] = {pk2(xa.x, xa.y), pk2(xa.z, xa.w),
                         pk2(xb.x, xb.y), pk2(xb.z, xb.w)};
            ull wn[8] = {bc2(wa.x), bc2(wa.y), bc2(wa.z), bc2(wa.w),
                         bc2(wb.x), bc2(wb.y), bc2(wb.z), bc2(wb.w)};
#pragma unroll
            for (int p = 0; p < 4; p++)
#pragma unroll
                for (int j = 0; j < 8; j++)
                    fma2(acc2[p][j], xp[p], wn[j]);
        }
        __syncthreads();
    }
    float bb[8];
#pragma unroll
    for (int j = 0; j < 8; j++) bb[j] = bias[bn + col0 + j];
#pragma unroll
    for (int p = 0; p < 4; p++) {
        float r0[8], r1[8];
#pragma unroll
        for (int j = 0; j < 8; j++) {
            float2 t = up2(acc2[p][j]);
            r0[j] = t.x + bb[j];
            r1[j] = t.y + bb[j];
        }
        float* y0 = &Y[(size_t)(bm + row0 + 2 * p) * N + bn + col0];
        *(float4*)y0 = make_float4(r0[0], r0[1], r0[2], r0[3]);
        *(float4*)(y0 + 4) = make_float4(r0[4], r0[5], r0[6], r0[7]);
        float* y1 = y0 + N;
        *(float4*)y1 = make_float4(r1[0], r1[1], r1[2], r1[3]);
        *(float4*)(y1 + 4) = make_float4(r1[4], r1[5], r1[6], r1[7]);
    }
}

__global__ void vsum_zero_kernel() { g_vsum[threadIdx.x] = 0.f; }

__global__ __launch_bounds__(256) void vsum_kernel()
{
    __shared__ float red[8][128];
    int b = blockIdx.x, part = blockIdx.y;
    int c4 = (threadIdx.x & 31) * 4;
    int r0 = threadIdx.x >> 5;
    const float* base = g_v + ((size_t)b * LK + part * 128) * QKV_N;
    float4 s = make_float4(0.f, 0.f, 0.f, 0.f);
#pragma unroll 4
    for (int r = r0; r < 128; r += 8) {
        float4 v = *(const float4*)&base[(size_t)r * QKV_N + c4];
        s.x += v.x; s.y += v.y; s.z += v.z; s.w += v.w;
    }
    *(float4*)&red[r0][c4] = s;
    __syncthreads();
    if (threadIdx.x < 128) {
        float t = 0.f;
#pragma unroll
        for (int i = 0; i < 8; i++) t += red[i][threadIdx.x];
        atomicAdd(&g_vsum[b * QKV_N + threadIdx.x], t);
    }
}

// streaming lse fix-up: attn[row][*] -= lse[row]; 2 rows per block
__global__ __launch_bounds__(256) void lse_fix_kernel(float* __restrict__ attn)
{
    int row = blockIdx.x * 2 + (threadIdx.x >> 7);
    int lane = threadIdx.x & 127;
    float l = g_lse[row];
    float* p = attn + (size_t)row * LK;
#pragma unroll
    for (int j = 0; j < 4; j++) {
        float* q = p + (lane + j * 128) * 4;
        float4 a = ld_cs4(q);
        a.x -= l; a.y -= l; a.z -= l; a.w -= l;
        st_cs4(q, a);
    }
}

// one block = 128 queries for one (b,h); double-buffered cp.async K/V pipeline
__global__ __launch_bounds__(256) void mab_main_kernel(
    const void* __restrict__ maskp, float* __restrict__ attn)
{
    extern __shared__ float sm[];
    int tid = threadIdx.x;
    int tx = tid & 15, ty = tid >> 4;
    int m0 = ty * 8;
    int nk = tx * 8;
    int nv = tx * 4;
    int q0 = blockIdx.x * BQ;
    int h = blockIdx.y, b = blockIdx.z;
    int mode = g_mask_mode;

    const float* qtbase = g_qT + ((size_t)(b * QKV_N + h * DK)) * LQ + q0;
    const float* ktbase = g_kT + ((size_t)(b * QKV_N + h * DK)) * LK;
    const float* vbase  = g_v + (size_t)b * LK * QKV_N + h * DK;
    float* arow = attn + ((size_t)((b * NH + h) * LQ + q0)) * LK;

    // prologue: Q tile + K(0) + V(0) via cp.async (one group)
#pragma unroll
    for (int i = 0; i < 8; i++) {
        int lin = tid + i * 256;
        int d = lin >> 5, qq = (lin & 31) * 4;
        cp_async16(smem_u32(&sm[OFF_Q + d * 128 + qq]), &qtbase[(size_t)d * LQ + qq]);
    }
#pragma unroll
    for (int i = 0; i < 8; i++) {
        int lin = tid + i * 256;
        int d = lin >> 5, kk = (lin & 31) * 4;
        cp_async16(smem_u32(&sm[OFF_K0 + d * 128 + kk]), &ktbase[(size_t)d * LK + kk]);
    }
#pragma unroll
    for (int i = 0; i < 8; i++) {
        int lin = tid + i * 256;
        int kr = lin >> 4, dv = (lin & 15) * 4;
        cp_async16(smem_u32(&sm[OFF_V0 + kr * DV + dv]), &vbase[(size_t)kr * QKV_N + dv]);
    }
    cp_commit();
    float mreg = 0.f;
    if (tid < BK) mreg = mask_at(maskp, mode, (size_t)b * LK + tid);
    if (tid < BQ) sm[OFF_RL + tid] = 0.f;

    ull sv2[4][4];
#pragma unroll
    for (int i = 0; i < 4; i++)
#pragma unroll
        for (int j = 0; j < 4; j++) sv2[i][j] = 0ull;

    for (int c = 0; c < LK / BK; c++) {
        int k0 = c * BK;
        int kbuf = (c & 1) ? OFF_K1 : OFF_K0;
        int vbuf = (c & 1) ? OFF_V1 : OFF_V0;
        int mbuf = OFF_MSK + (c & 1) * 128;
        if (tid < BK) sm[mbuf + tid] = mreg;   // mask(c); no reader conflicts
        cp_wait0();                             // group(c) landed
        __syncthreads();                        // B: data visible; prev phases done

        if (c < 15) {
            // issue group(c+1) now: its buffers were last read in phase1/2(c-1),
            // which all warps completed before barrier B above.
            int k1 = k0 + BK;
            int kb2 = (c & 1) ? OFF_K0 : OFF_K1;
            int vb2 = (c & 1) ? OFF_V0 : OFF_V1;
#pragma unroll
            for (int i = 0; i < 8; i++) {
                int lin = tid + i * 256;
                int d = lin >> 5, kk = (lin & 31) * 4;
                cp_async16(smem_u32(&sm[kb2 + d * 128 + kk]),
                           &ktbase[(size_t)d * LK + k1 + kk]);
            }
#pragma unroll
            for (int i = 0; i < 8; i++) {
                int lin = tid + i * 256;
                int kr = lin >> 4, dv = (lin & 15) * 4;
                cp_async16(smem_u32(&sm[vb2 + kr * DV + dv]),
                           &vbase[(size_t)(k1 + kr) * QKV_N + dv]);
            }
            cp_commit();
            if (tid < BK) mreg = mask_at(maskp, mode, (size_t)b * LK + k1 + tid);
        }

        // phase 1: S = q @ k^T, 8 queries x 8 keys per thread
        ull acc2[4][8];
#pragma unroll
        for (int p = 0; p < 4; p++)
#pragma unroll
            for (int j = 0; j < 8; j++) acc2[p][j] = 0ull;

#pragma unroll 4
        for (int d = 0; d < DK; d++) {
            float4 qa = *(const float4*)&sm[OFF_Q + d * 128 + m0];
            float4 qb = *(const float4*)&sm[OFF_Q + d * 128 + m0 + 4];
            float4 ka = *(const float4*)&sm[kbuf + d * 128 + nk];
            float4 kb4 = *(const float4*)&sm[kbuf + d * 128 + nk + 4];
            ull qp[4] = {pk2(qa.x, qa.y), pk2(qa.z, qa.w),
                         pk2(qb.x, qb.y), pk2(qb.z, qb.w)};
            ull kb[8] = {bc2(ka.x), bc2(ka.y), bc2(ka.z), bc2(ka.w),
                         bc2(kb4.x), bc2(kb4.y), bc2(kb4.z), bc2(kb4.w)};
#pragma unroll
            for (int p = 0; p < 4; p++)
#pragma unroll
                for (int j = 0; j < 8; j++)
                    fma2(acc2[p][j], qp[p], kb[j]);
        }

        float acc[8][8];
#pragma unroll
        for (int p = 0; p < 4; p++)
#pragma unroll
            for (int j = 0; j < 8; j++) {
                float2 v = up2(acc2[p][j]);
                acc[2 * p][j] = v.x;
                acc[2 * p + 1][j] = v.y;
            }

        float mk[8];
#pragma unroll
        for (int j = 0; j < 8; j++) mk[j] = sm[mbuf + nk + j];

        float er[8];
#pragma unroll
        for (int i = 0; i < 8; i++) {
            float rs = 0.f;
#pragma unroll
            for (int j = 0; j < 8; j++) {
                float s = tanh10s(acc[i][j]);
                if (mk[j] != 0.f) s = -10.f;
                acc[i][j] = s;
                rs += __expf(s);
            }
            er[i] = rs;
            float* ap = &arow[(size_t)(m0 + i) * LK + k0 + nk];
            st_cs4(ap, make_float4(acc[i][0], acc[i][1], acc[i][2], acc[i][3]));
            st_cs4(ap + 4, make_float4(acc[i][4], acc[i][5], acc[i][6], acc[i][7]));
        }
#pragma unroll
        for (int d = 1; d < 16; d <<= 1) {
#pragma unroll
            for (int i = 0; i < 8; i++)
                er[i] += __shfl_xor_sync(0xffffffffu, er[i], d);
        }
        if (tx == 0) {
#pragma unroll
            for (int i = 0; i < 8; i++)
                sm[OFF_RL + m0 + i] += er[i];
        }
        {
            int g = m0 >> 2;
#pragma unroll
            for (int j = 0; j < 8; j++) {
                int kc = nk + j;
                *(float4*)&sm[s_off(kc, g)] =
                    make_float4(acc[0][j], acc[1][j], acc[2][j], acc[3][j]);
                *(float4*)&sm[s_off(kc, g + 1)] =
                    make_float4(acc[4][j], acc[5][j], acc[6][j], acc[7][j]);
            }
        }
        __syncthreads();   // C: S visible

        // phase 2: SV += S_chunk @ v_chunk (8 queries x 4 dv per thread)
        {
            int g = m0 >> 2;
#pragma unroll 8
            for (int kc = 0; kc < BK; kc++) {
                float4 sa = *(const float4*)&sm[s_off(kc, g)];
                float4 sb = *(const float4*)&sm[s_off(kc, g + 1)];
                float4 vv = *(const float4*)&sm[vbuf + kc * DV + nv];
                ull sp[4] = {pk2(sa.x, sa.y), pk2(sa.z, sa.w),
                             pk2(sb.x, sb.y), pk2(sb.z, sb.w)};
                ull vb[4] = {bc2(vv.x), bc2(vv.y), bc2(vv.z), bc2(vv.w)};
#pragma unroll
                for (int p = 0; p < 4; p++)
#pragma unroll
                    for (int j = 0; j < 4; j++)
                        fma2(sv2[p][j], sp[p], vb[j]);
            }
        }
    }

    __syncthreads();
    if (tid < BQ) {
        float l = logf(sm[OFF_RL + tid]);
        sm[OFF_LSE + tid] = l;
        g_lse[(b * NH + h) * LQ + q0 + tid] = l;
    }
    __syncthreads();

    {   // otmp = SV - lse * vsum
        float4 vs = *(const float4*)&g_vsum[(b * NH + h) * DV + nv];
#pragma unroll
        for (int p = 0; p < 4; p++) {
            float2 c0 = up2(sv2[p][0]), c1 = up2(sv2[p][1]);
            float2 c2 = up2(sv2[p][2]), c3 = up2(sv2[p][3]);
            float l0 = sm[OFF_LSE + m0 + 2 * p];
            float l1 = sm[OFF_LSE + m0 + 2 * p + 1];
            size_t r0 = ((size_t)b * LQ + q0 + m0 + 2 * p) * QKV_N + h * DK + nv;
            *(float4*)&g_otmp[r0] =
                make_float4(c0.x - l0 * vs.x, c1.x - l0 * vs.y,
                            c2.x - l0 * vs.z, c3.x - l0 * vs.w);
            *(float4*)&g_otmp[r0 + QKV_N] =
                make_float4(c0.y - l1 * vs.x, c1.y - l1 * vs.y,
                            c2.y - l1 * vs.z, c3.y - l1 * vs.w);
        }
    }
}

extern "C" void kernel_launch(void* const* d_in, const int* in_sizes, int n_in,
                              void* d_out, int out_size)
{
    const float* Q  = (const float*)d_in[0];
    const float* K  = (const float*)d_in[1];
    const float* V  = (const float*)d_in[2];
    const void*  Mk = d_in[3];
    const float* Wq = (const float*)d_in[4];
    const float* bq = (const float*)d_in[5];
    const float* Wk = (const float*)d_in[6];
    const float* bk = (const float*)d_in[7];
    const float* Wv = (const float*)d_in[8];
    const float* bv = (const float*)d_in[9];
    const float* Wo = (const float*)d_in[10];
    const float* bo = (const float*)d_in[11];

    float* out  = (float*)d_out;
    float* attn = out + (size_t)BATCH * LQ * DMODEL;

    float *gqt, *gkt, *gv, *gotmp;
    cudaGetSymbolAddress((void**)&gqt, g_qT);
    cudaGetSymbolAddress((void**)&gkt, g_kT);
    cudaGetSymbolAddress((void**)&gv, g_v);
    cudaGetSymbolAddress((void**)&gotmp, g_otmp);

    static int smem_set = 0;
    if (!smem_set) {
        cudaFuncSetAttribute(mab_main_kernel,
                             cudaFuncAttributeMaxDynamicSharedMemorySize, SMEM_BYTES);
        smem_set = 1;
    }

    detect_mask_kernel<<<1, 256>>>((const unsigned int*)Mk);

    const int M = BATCH * LQ;  // 8192
    gemm_qkv_kernel<<<dim3(M / 128, 3), 256>>>(Q, K, V, Wq, Wk, Wv,
                                               bq, bk, bv, gqt, gkt, gv);

    vsum_zero_kernel<<<1, BATCH * QKV_N>>>();
    vsum_kernel<<<dim3(BATCH, 16), 256>>>();

    mab_main_kernel<<<dim3(LQ / BQ, NH, BATCH), 256, SMEM_BYTES>>>(Mk, attn);

    lse_fix_kernel<<<BATCH * NH * LQ / 2, 256>>>(attn);

    gemm_bias128_kernel<<<dim3(M / 128, DMODEL / 128), 256>>>(gotmp, Wo, bo, out,
                                                              M, QKV_N, DMODEL);
}

// round 13
// speedup vs baseline: 1.3386x; 1.0932x over previous
#include <cuda_runtime.h>
#include <math.h>

#define BATCH 4
#define LQ 2048
#define LK 2048
#define DMODEL 512
#define NH 2
#define DK 64
#define DV 64
#define QKV_N 128

#define BQ 128
#define BK 128

// unpadded smem layout (floats)
#define OFF_Q 0
#define OFF_K0 8192
#define OFF_K1 16384
#define OFF_V0 24576
#define OFF_V1 32768
#define OFF_S 40960
#define OFF_RL 57344
#define OFF_LSE 57472
#define OFF_MSK 57600      // double-buffered mask: 2 x 128
#define SMEM_FLOATS 57856
#define SMEM_BYTES (SMEM_FLOATS * 4)   // 231424 <= 232448 max

typedef unsigned long long ull;

__device__ __forceinline__ ull pk2(float x, float y)
{ ull r; asm("mov.b64 %0,{%1,%2};" : "=l"(r) : "f"(x), "f"(y)); return r; }
__device__ __forceinline__ ull bc2(float x) { return pk2(x, x); }
__device__ __forceinline__ void fma2(ull& d, ull a, ull b)
{ asm("fma.rn.f32x2 %0,%1,%2,%0;" : "+l"(d) : "l"(a), "l"(b)); }
__device__ __forceinline__ float2 up2(ull v)
{ float2 r; asm("mov.b64 {%0,%1},%2;" : "=f"(r.x), "=f"(r.y) : "l"(v)); return r; }

__device__ __forceinline__ unsigned smem_u32(const void* p)
{
    unsigned a;
    asm("{ .reg .u64 t; cvta.to.shared.u64 t, %1; cvt.u32.u64 %0, t; }"
        : "=r"(a) : "l"(p));
    return a;
}
__device__ __forceinline__ void cp_async16(unsigned dst, const void* src)
{ asm volatile("cp.async.cg.shared.global [%0],[%1],16;" :: "r"(dst), "l"(src)); }
__device__ __forceinline__ void cp_commit()
{ asm volatile("cp.async.commit_group;"); }
__device__ __forceinline__ void cp_wait0()
{ asm volatile("cp.async.wait_group 0;"); }

__device__ __forceinline__ void st_cs4(float* p, float4 v)
{ asm volatile("st.global.cs.v4.f32 [%0],{%1,%2,%3,%4};"
               :: "l"(p), "f"(v.x), "f"(v.y), "f"(v.z), "f"(v.w) : "memory"); }
__device__ __forceinline__ float4 ld_cs4(const float* p)
{
    float4 v;
    asm volatile("ld.global.cs.v4.f32 {%0,%1,%2,%3},[%4];"
                 : "=f"(v.x), "=f"(v.y), "=f"(v.z), "=f"(v.w) : "l"(p));
    return v;
}

__device__ __forceinline__ int s_off(int kc, int g)
{ return OFF_S + kc * BQ + (((g + kc + (kc >> 3)) & 31) << 2); }

// 10*tanh(0.125*x) = 10 - 20/(exp(0.25x)+1); exact at +/-inf
__device__ __forceinline__ float tanh10s(float x)
{
    float e = __expf(0.25f * x);
    float r;
    asm("rcp.approx.f32 %0,%1;" : "=f"(r) : "f"(e + 1.f));
    return fmaf(-20.f, r, 10.f);
}

__device__ float g_qT[BATCH * QKV_N * LQ];   // [b*128 + col][l]
__device__ float g_kT[BATCH * QKV_N * LK];   // [b*128 + col][l]
__device__ float g_v[BATCH * LK * QKV_N];    // natural
__device__ float g_otmp[BATCH * LQ * QKV_N];
__device__ float g_vsum[BATCH * QKV_N];
__device__ float g_lse[BATCH * NH * LQ];
__device__ int g_mask_mode;  // 0=u8, 1=i32, 2=f32

__device__ __forceinline__ float mask_at(const void* p, int mode, size_t gi)
{
    if (mode == 1) return ((const int*)p)[gi] != 0 ? 1.f : 0.f;
    if (mode == 0) return ((const unsigned char*)p)[gi] != 0 ? 1.f : 0.f;
    return ((const float*)p)[gi] != 0.f ? 1.f : 0.f;
}

__global__ void detect_mask_kernel(const unsigned int* __restrict__ w)
{
    __shared__ int s_f32, s_all01;
    if (threadIdx.x == 0) { s_f32 = 0; s_all01 = 1; }
    __syncthreads();
    int f = 0, bad = 0;
    for (int i = threadIdx.x; i < 2048; i += blockDim.x) {
        unsigned v = w[i];
        if (v == 0x3F800000u) f = 1;
        if (v > 1u) bad = 1;
    }
    if (f) atomicOr(&s_f32, 1);
    if (bad) atomicExch(&s_all01, 0);
    __syncthreads();
    if (threadIdx.x == 0) g_mask_mode = s_f32 ? 2 : (s_all01 ? 1 : 0);
}

// ---- fused QKV projection: 64x128 tile, 128 threads, 8x8 frags.
// sel 0 (Q) and 1 (K) write TRANSPOSED output [b*128+col][l]; sel 2 (V) natural.
__global__ __launch_bounds__(128) void gemm_qkv_kernel(
    const float* __restrict__ X0, const float* __restrict__ X1, const float* __restrict__ X2,
    const float* __restrict__ W0, const float* __restrict__ W1, const float* __restrict__ W2,
    const float* __restrict__ B0, const float* __restrict__ B1, const float* __restrict__ B2,
    float* __restrict__ Y0, float* __restrict__ Y1, float* __restrict__ Y2)
{
    __shared__ float xs[32 * 68];
    __shared__ float ws[32 * 132];
    int sel = blockIdx.y;
    const float* X = sel == 0 ? X0 : (sel == 1 ? X1 : X2);
    const float* W = sel == 0 ? W0 : (sel == 1 ? W1 : W2);
    const float* bias = sel == 0 ? B0 : (sel == 1 ? B1 : B2);
    float* Y = sel == 0 ? Y0 : (sel == 1 ? Y1 : Y2);

    int tid = threadIdx.x;
    int tx = tid & 15, ty = tid >> 4;        // tx 0..15, ty 0..7
    int bm = blockIdx.x * 64;
    int row0 = ty * 8, col0 = tx * 8;

    ull acc2[4][8];
#pragma unroll
    for (int p = 0; p < 4; p++)
#pragma unroll
        for (int j = 0; j < 8; j++) acc2[p][j] = 0ull;

    for (int k0 = 0; k0 < DMODEL; k0 += 32) {
#pragma unroll
        for (int i = 0; i < 4; i++) {
            int linear = tid + i * 128;
            int m = linear >> 3;
            int g = (linear & 7) * 4;
            float4 v = *(const float4*)&X[(size_t)(bm + m) * DMODEL + k0 + g];
            xs[(g + 0) * 68 + m] = v.x;
            xs[(g + 1) * 68 + m] = v.y;
            xs[(g + 2) * 68 + m] = v.z;
            xs[(g + 3) * 68 + m] = v.w;
        }
#pragma unroll
        for (int i = 0; i < 8; i++) {
            int linear = tid + i * 128;
            int k = linear >> 5;
            int g = (linear & 31) * 4;
            *(float4*)&ws[k * 132 + g] = *(const float4*)&W[(size_t)(k0 + k) * QKV_N + g];
        }
        __syncthreads();
#pragma unroll
        for (int k = 0; k < 32; k++) {
            float4 xa = *(const float4*)&xs[k * 68 + row0];
            float4 xb = *(const float4*)&xs[k * 68 + row0 + 4];
            float4 wa = *(const float4*)&ws[k * 132 + col0];
            float4 wb = *(const float4*)&ws[k * 132 + col0 + 4];
            ull xp[4] = {pk2(xa.x, xa.y), pk2(xa.z, xa.w),
                         pk2(xb.x, xb.y), pk2(xb.z, xb.w)};
            ull wn[8] = {bc2(wa.x), bc2(wa.y), bc2(wa.z), bc2(wa.w),
                         bc2(wb.x), bc2(wb.y), bc2(wb.z), bc2(wb.w)};
#pragma unroll
            for (int p = 0; p < 4; p++)
#pragma unroll
                for (int j = 0; j < 8; j++)
                    fma2(acc2[p][j], xp[p], wn[j]);
        }
        __syncthreads();
    }
    float bb[8];
#pragma unroll
    for (int j = 0; j < 8; j++) bb[j] = bias[col0 + j];

    if (sel == 2) {
#pragma unroll
        for (int p = 0; p < 4; p++) {
            float r0[8], r1[8];
#pragma unroll
            for (int j = 0; j < 8; j++) {
                float2 t = up2(acc2[p][j]);
                r0[j] = t.x + bb[j];
                r1[j] = t.y + bb[j];
            }
            float* y0 = &Y[(size_t)(bm + row0 + 2 * p) * QKV_N + col0];
            *(float4*)y0 = make_float4(r0[0], r0[1], r0[2], r0[3]);
            *(float4*)(y0 + 4) = make_float4(r0[4], r0[5], r0[6], r0[7]);
            float* y1 = y0 + QKV_N;
            *(float4*)y1 = make_float4(r1[0], r1[1], r1[2], r1[3]);
            *(float4*)(y1 + 4) = make_float4(r1[4], r1[5], r1[6], r1[7]);
        }
    } else {
        int b = bm >> 11;
        int l0 = (bm & 2047) + row0;
#pragma unroll
        for (int j = 0; j < 8; j++) {
            float v[8];
#pragma unroll
            for (int p = 0; p < 4; p++) {
                float2 t = up2(acc2[p][j]);
                v[2 * p] = t.x + bb[j];
                v[2 * p + 1] = t.y + bb[j];
            }
            float* yp = &Y[((size_t)(b * QKV_N + col0 + j)) * LQ + l0];
            *(float4*)yp = make_float4(v[0], v[1], v[2], v[3]);
            *(float4*)(yp + 4) = make_float4(v[4], v[5], v[6], v[7]);
        }
    }
}

// ---- out-proj GEMM, 128x128 tile, 8x8 frags
__global__ __launch_bounds__(256) void gemm_bias128_kernel(
    const float* __restrict__ X, const float* __restrict__ W,
    const float* __restrict__ bias, float* __restrict__ Y,
    int M, int K, int N)
{
    __shared__ float xs[32 * 132];
    __shared__ float ws[32 * 132];
    int tid = threadIdx.x;
    int tx = tid & 15, ty = tid >> 4;
    int bm = blockIdx.x * 128, bn = blockIdx.y * 128;
    int row0 = ty * 8, col0 = tx * 8;

    ull acc2[4][8];
#pragma unroll
    for (int p = 0; p < 4; p++)
#pragma unroll
        for (int j = 0; j < 8; j++) acc2[p][j] = 0ull;

    for (int k0 = 0; k0 < K; k0 += 32) {
#pragma unroll
        for (int i = 0; i < 4; i++) {
            int linear = tid + i * 256;
            int m = linear >> 3;
            int g = (linear & 7) * 4;
            float4 v = *(const float4*)&X[(size_t)(bm + m) * K + k0 + g];
            xs[(g + 0) * 132 + m] = v.x;
            xs[(g + 1) * 132 + m] = v.y;
            xs[(g + 2) * 132 + m] = v.z;
            xs[(g + 3) * 132 + m] = v.w;
        }
#pragma unroll
        for (int i = 0; i < 4; i++) {
            int linear = tid + i * 256;
            int k = linear >> 5;
            int g = (linear & 31) * 4;
            *(float4*)&ws[k * 132 + g] = *(const float4*)&W[(size_t)(k0 + k) * N + bn + g];
        }
        __syncthreads();
#pragma unroll
        for (int k = 0; k < 32; k++) {
            float4 xa = *(const float4*)&xs[k * 132 + row0];
            float4 xb = *(const float4*)&xs[k * 132 + row0 + 4];
            float4 wa = *(const float4*)&ws[k * 132 + col0];
            float4 wb = *(const float4*)&ws[k * 132 + col0 + 4];
            ull xp[4] = {pk2(xa.x, xa.y), pk2(xa.z, xa.w),
                         pk2(xb.x, xb.y), pk2(xb.z, xb.w)};
            ull wn[8] = {bc2(wa.x), bc2(wa.y), bc2(wa.z), bc2(wa.w),
                         bc2(wb.x), bc2(wb.y), bc2(wb.z), bc2(wb.w)};
#pragma unroll
            for (int p = 0; p < 4; p++)
#pragma unroll
                for (int j = 0; j < 8; j++)
                    fma2(acc2[p][j], xp[p], wn[j]);
        }
        __syncthreads();
    }
    float bb[8];
#pragma unroll
    for (int j = 0; j < 8; j++) bb[j] = bias[bn + col0 + j];
#pragma unroll
    for (int p = 0; p < 4; p++) {
        float r0[8], r1[8];
#pragma unroll
        for (int j = 0; j < 8; j++) {
            float2 t = up2(acc2[p][j]);
            r0[j] = t.x + bb[j];
            r1[j] = t.y + bb[j];
        }
        float* y0 = &Y[(size_t)(bm + row0 + 2 * p) * N + bn + col0];
        *(float4*)y0 = make_float4(r0[0], r0[1], r0[2], r0[3]);
        *(float4*)(y0 + 4) = make_float4(r0[4], r0[5], r0[6], r0[7]);
        float* y1 = y0 + N;
        *(float4*)y1 = make_float4(r1[0], r1[1], r1[2], r1[3]);
        *(float4*)(y1 + 4) = make_float4(r1[4], r1[5], r1[6], r1[7]);
    }
}

__global__ void vsum_zero_kernel() { g_vsum[threadIdx.x] = 0.f; }

__global__ __launch_bounds__(256) void vsum_kernel()
{
    __shared__ float red[8][128];
    int b = blockIdx.x, part = blockIdx.y;
    int c4 = (threadIdx.x & 31) * 4;
    int r0 = threadIdx.x >> 5;
    const float* base = g_v + ((size_t)b * LK + part * 128) * QKV_N;
    float4 s = make_float4(0.f, 0.f, 0.f, 0.f);
#pragma unroll 4
    for (int r = r0; r < 128; r += 8) {
        float4 v = *(const float4*)&base[(size_t)r * QKV_N + c4];
        s.x += v.x; s.y += v.y; s.z += v.z; s.w += v.w;
    }
    *(float4*)&red[r0][c4] = s;
    __syncthreads();
    if (threadIdx.x < 128) {
        float t = 0.f;
#pragma unroll
        for (int i = 0; i < 8; i++) t += red[i][threadIdx.x];
        atomicAdd(&g_vsum[b * QKV_N + threadIdx.x], t);
    }
}

// streaming lse fix-up: attn[row][*] -= lse[row]; 2 rows per block
__global__ __launch_bounds__(256) void lse_fix_kernel(float* __restrict__ attn)
{
    int row = blockIdx.x * 2 + (threadIdx.x >> 7);
    int lane = threadIdx.x & 127;
    float l = g_lse[row];
    float* p = attn + (size_t)row * LK;
#pragma unroll
    for (int j = 0; j < 4; j++) {
        float* q = p + (lane + j * 128) * 4;
        float4 a = ld_cs4(q);
        a.x -= l; a.y -= l; a.z -= l; a.w -= l;
        st_cs4(q, a);
    }
}

// one block = 128 queries for one (b,h); double-buffered cp.async K/V pipeline
__global__ __launch_bounds__(256) void mab_main_kernel(
    const void* __restrict__ maskp, float* __restrict__ attn)
{
    extern __shared__ float sm[];
    int tid = threadIdx.x;
    int tx = tid & 15, ty = tid >> 4;
    int m0 = ty * 8;
    int nk = tx * 8;
    int nv = tx * 4;
    int q0 = blockIdx.x * BQ;
    int h = blockIdx.y, b = blockIdx.z;
    int mode = g_mask_mode;

    const float* qtbase = g_qT + ((size_t)(b * QKV_N + h * DK)) * LQ + q0;
    const float* ktbase = g_kT + ((size_t)(b * QKV_N + h * DK)) * LK;
    const float* vbase  = g_v + (size_t)b * LK * QKV_N + h * DK;
    float* arow = attn + ((size_t)((b * NH + h) * LQ + q0)) * LK;

    // prologue: Q tile + K(0) + V(0) via cp.async (one group)
#pragma unroll
    for (int i = 0; i < 8; i++) {
        int lin = tid + i * 256;
        int d = lin >> 5, qq = (lin & 31) * 4;
        cp_async16(smem_u32(&sm[OFF_Q + d * 128 + qq]), &qtbase[(size_t)d * LQ + qq]);
    }
#pragma unroll
    for (int i = 0; i < 8; i++) {
        int lin = tid + i * 256;
        int d = lin >> 5, kk = (lin & 31) * 4;
        cp_async16(smem_u32(&sm[OFF_K0 + d * 128 + kk]), &ktbase[(size_t)d * LK + kk]);
    }
#pragma unroll
    for (int i = 0; i < 8; i++) {
        int lin = tid + i * 256;
        int kr = lin >> 4, dv = (lin & 15) * 4;
        cp_async16(smem_u32(&sm[OFF_V0 + kr * DV + dv]), &vbase[(size_t)kr * QKV_N + dv]);
    }
    cp_commit();
    float mreg = 0.f;
    if (tid < BK) mreg = mask_at(maskp, mode, (size_t)b * LK + tid);
    if (tid < BQ) sm[OFF_RL + tid] = 0.f;

    ull sv2[4][4];
#pragma unroll
    for (int i = 0; i < 4; i++)
#pragma unroll
        for (int j = 0; j < 4; j++) sv2[i][j] = 0ull;

    for (int c = 0; c < LK / BK; c++) {
        int k0 = c * BK;
        int kbuf = (c & 1) ? OFF_K1 : OFF_K0;
        int vbuf = (c & 1) ? OFF_V1 : OFF_V0;
        int mbuf = OFF_MSK + (c & 1) * 128;
        if (tid < BK) sm[mbuf + tid] = mreg;   // mask(c); no reader conflicts
        cp_wait0();                             // group(c) landed
        __syncthreads();                        // B: data visible; prev phases done

        if (c < 15) {
            int k1 = k0 + BK;
            int kb2 = (c & 1) ? OFF_K0 : OFF_K1;
            int vb2 = (c & 1) ? OFF_V0 : OFF_V1;
#pragma unroll
            for (int i = 0; i < 8; i++) {
                int lin = tid + i * 256;
                int d = lin >> 5, kk = (lin & 31) * 4;
                cp_async16(smem_u32(&sm[kb2 + d * 128 + kk]),
                           &ktbase[(size_t)d * LK + k1 + kk]);
            }
#pragma unroll
            for (int i = 0; i < 8; i++) {
                int lin = tid + i * 256;
                int kr = lin >> 4, dv = (lin & 15) * 4;
                cp_async16(smem_u32(&sm[vb2 + kr * DV + dv]),
                           &vbase[(size_t)(k1 + kr) * QKV_N + dv]);
            }
            cp_commit();
            if (tid < BK) mreg = mask_at(maskp, mode, (size_t)b * LK + k1 + tid);
        }

        // phase 1: S = q @ k^T, 8 queries x 8 keys per thread
        ull acc2[4][8];
#pragma unroll
        for (int p = 0; p < 4; p++)
#pragma unroll
            for (int j = 0; j < 8; j++) acc2[p][j] = 0ull;

#pragma unroll 4
        for (int d = 0; d < DK; d++) {
            float4 qa = *(const float4*)&sm[OFF_Q + d * 128 + m0];
            float4 qb = *(const float4*)&sm[OFF_Q + d * 128 + m0 + 4];
            float4 ka = *(const float4*)&sm[kbuf + d * 128 + nk];
            float4 kb4 = *(const float4*)&sm[kbuf + d * 128 + nk + 4];
            ull qp[4] = {pk2(qa.x, qa.y), pk2(qa.z, qa.w),
                         pk2(qb.x, qb.y), pk2(qb.z, qb.w)};
            ull kb[8] = {bc2(ka.x), bc2(ka.y), bc2(ka.z), bc2(ka.w),
                         bc2(kb4.x), bc2(kb4.y), bc2(kb4.z), bc2(kb4.w)};
#pragma unroll
            for (int p = 0; p < 4; p++)
#pragma unroll
                for (int j = 0; j < 8; j++)
                    fma2(acc2[p][j], qp[p], kb[j]);
        }

        float acc[8][8];
#pragma unroll
        for (int p = 0; p < 4; p++)
#pragma unroll
            for (int j = 0; j < 8; j++) {
                float2 v = up2(acc2[p][j]);
                acc[2 * p][j] = v.x;
                acc[2 * p + 1][j] = v.y;
            }

        float mk[8];
#pragma unroll
        for (int j = 0; j < 8; j++) mk[j] = sm[mbuf + nk + j];

        float er[8];
#pragma unroll
        for (int i = 0; i < 8; i++) {
            float rs = 0.f;
#pragma unroll
            for (int j = 0; j < 8; j++) {
                float s = tanh10s(acc[i][j]);
                if (mk[j] != 0.f) s = -10.f;
                acc[i][j] = s;
                rs += __expf(s);
            }
            er[i] = rs;
            float* ap = &arow[(size_t)(m0 + i) * LK + k0 + nk];
            st_cs4(ap, make_float4(acc[i][0], acc[i][1], acc[i][2], acc[i][3]));
            st_cs4(ap + 4, make_float4(acc[i][4], acc[i][5], acc[i][6], acc[i][7]));
        }
#pragma unroll
        for (int d = 1; d < 16; d <<= 1) {
#pragma unroll
            for (int i = 0; i < 8; i++)
                er[i] += __shfl_xor_sync(0xffffffffu, er[i], d);
        }
        if (tx == 0) {
#pragma unroll
            for (int i = 0; i < 8; i++)
                sm[OFF_RL + m0 + i] += er[i];
        }
        {
            int g = m0 >> 2;
#pragma unroll
            for (int j = 0; j < 8; j++) {
                int kc = nk + j;
                *(float4*)&sm[s_off(kc, g)] =
                    make_float4(acc[0][j], acc[1][j], acc[2][j], acc[3][j]);
                *(float4*)&sm[s_off(kc, g + 1)] =
                    make_float4(acc[4][j], acc[5][j], acc[6][j], acc[7][j]);
            }
        }
        __syncthreads();   // C: S visible

        // phase 2: SV += S_chunk @ v_chunk (8 queries x 4 dv per thread)
        {
            int g = m0 >> 2;
#pragma unroll 8
            for (int kc = 0; kc < BK; kc++) {
                float4 sa = *(const float4*)&sm[s_off(kc, g)];
                float4 sb = *(const float4*)&sm[s_off(kc, g + 1)];
                float4 vv = *(const float4*)&sm[vbuf + kc * DV + nv];
                ull sp[4] = {pk2(sa.x, sa.y), pk2(sa.z, sa.w),
                             pk2(sb.x, sb.y), pk2(sb.z, sb.w)};
                ull vb[4] = {bc2(vv.x), bc2(vv.y), bc2(vv.z), bc2(vv.w)};
#pragma unroll
                for (int p = 0; p < 4; p++)
#pragma unroll
                    for (int j = 0; j < 4; j++)
                        fma2(sv2[p][j], sp[p], vb[j]);
            }
        }
    }

    __syncthreads();
    if (tid < BQ) {
        float l = logf(sm[OFF_RL + tid]);
        sm[OFF_LSE + tid] = l;
        g_lse[(b * NH + h) * LQ + q0 + tid] = l;
    }
    __syncthreads();

    {   // otmp = SV - lse * vsum
        float4 vs = *(const float4*)&g_vsum[(b * NH + h) * DV + nv];
#pragma unroll
        for (int p = 0; p < 4; p++) {
            float2 c0 = up2(sv2[p][0]), c1 = up2(sv2[p][1]);
            float2 c2 = up2(sv2[p][2]), c3 = up2(sv2[p][3]);
            float l0 = sm[OFF_LSE + m0 + 2 * p];
            float l1 = sm[OFF_LSE + m0 + 2 * p + 1];
            size_t r0 = ((size_t)b * LQ + q0 + m0 + 2 * p) * QKV_N + h * DK + nv;
            *(float4*)&g_otmp[r0] =
                make_float4(c0.x - l0 * vs.x, c1.x - l0 * vs.y,
                            c2.x - l0 * vs.z, c3.x - l0 * vs.w);
            *(float4*)&g_otmp[r0 + QKV_N] =
                make_float4(c0.y - l1 * vs.x, c1.y - l1 * vs.y,
                            c2.y - l1 * vs.z, c3.y - l1 * vs.w);
        }
    }
}

extern "C" void kernel_launch(void* const* d_in, const int* in_sizes, int n_in,
                              void* d_out, int out_size)
{
    const float* Q  = (const float*)d_in[0];
    const float* K  = (const float*)d_in[1];
    const float* V  = (const float*)d_in[2];
    const void*  Mk = d_in[3];
    const float* Wq = (const float*)d_in[4];
    const float* bq = (const float*)d_in[5];
    const float* Wk = (const float*)d_in[6];
    const float* bk = (const float*)d_in[7];
    const float* Wv = (const float*)d_in[8];
    const float* bv = (const float*)d_in[9];
    const float* Wo = (const float*)d_in[10];
    const float* bo = (const float*)d_in[11];

    float* out  = (float*)d_out;
    float* attn = out + (size_t)BATCH * LQ * DMODEL;

    float *gqt, *gkt, *gv, *gotmp;
    cudaGetSymbolAddress((void**)&gqt, g_qT);
    cudaGetSymbolAddress((void**)&gkt, g_kT);
    cudaGetSymbolAddress((void**)&gv, g_v);
    cudaGetSymbolAddress((void**)&gotmp, g_otmp);

    static int inited = 0;
    static cudaStream_t s2;
    static cudaEvent_t evFork, evJoin;
    if (!inited) {
        cudaFuncSetAttribute(mab_main_kernel,
                             cudaFuncAttributeMaxDynamicSharedMemorySize, SMEM_BYTES);
        cudaStreamCreateWithFlags(&s2, cudaStreamNonBlocking);
        cudaEventCreateWithFlags(&evFork, cudaEventDisableTiming);
        cudaEventCreateWithFlags(&evJoin, cudaEventDisableTiming);
        inited = 1;
    }

    detect_mask_kernel<<<1, 256>>>((const unsigned int*)Mk);

    const int M = BATCH * LQ;  // 8192
    gemm_qkv_kernel<<<dim3(M / 64, 3), 128>>>(Q, K, V, Wq, Wk, Wv,
                                              bq, bk, bv, gqt, gkt, gv);

    vsum_zero_kernel<<<1, BATCH * QKV_N>>>();
    vsum_kernel<<<dim3(BATCH, 16), 256>>>();

    mab_main_kernel<<<dim3(LQ / BQ, NH, BATCH), 256, SMEM_BYTES>>>(Mk, attn);

    // fork: lse fix-up (DRAM-bound) runs parallel to out-proj (compute-bound)
    cudaEventRecord(evFork, 0);
    cudaStreamWaitEvent(s2, evFork, 0);
    lse_fix_kernel<<<BATCH * NH * LQ / 2, 256, 0, s2>>>(attn);
    cudaEventRecord(evJoin, s2);

    gemm_bias128_kernel<<<dim3(M / 128, DMODEL / 128), 256>>>(gotmp, Wo, bo, out,
                                                              M, QKV_N, DMODEL);
    cudaStreamWaitEvent(0, evJoin, 0);
}